// round 12
// baseline (speedup 1.0000x reference)
#include <cuda_runtime.h>
#include <math.h>
#include <stddef.h>

#define BSZ 256
#define SSZ 128
#define ESZ 256
#define HSZ 512
#define GSZ 2048   // 4*H
#define NC  2560   // 2048 gates + 512 (proj or q)
#define NB2 4096   // 2*GSZ combined xg cols
#define NBLK 128   // persistent grid size

// ---------- device scratch ----------
__device__ float  g_WencT[HSZ * NC];
__device__ float  g_WdecT[HSZ * NC];
__device__ float  g_WihT[ESZ * NB2];
__device__ float  g_emb[(size_t)BSZ * SSZ * ESZ];
__device__ float  g_xg_enc[(size_t)BSZ * SSZ * GSZ];
__device__ float  g_xg_dec[(size_t)BSZ * SSZ * GSZ];
__device__ float  g_proj[(size_t)BSZ * SSZ * HSZ];
__device__ float  g_C[BSZ * GSZ];
__device__ float  g_h[2][BSZ * HSZ];
__device__ float  g_c[BSZ * HSZ];
__device__ float  g_q[BSZ * HSZ];
__device__ float  g_xg0[GSZ];
__device__ int    g_mask[BSZ * SSZ];
__device__ int    g_barGen;
__device__ int    g_barCnt;

// ---------- frozen numerics: libdevice tanh, exp-based logistic ----------
__device__ __forceinline__ float xtanh(float x) { return tanhf(x); }
__device__ __forceinline__ float sigf(float x) {
    return __fdiv_rn(1.0f, __fadd_rn(1.0f, expf(-x)));
}

// ---------- weight transposes ----------
__global__ void transpose_kernel(const float* __restrict__ encWhh, const float* __restrict__ W1,
                                 const float* __restrict__ decWhh, const float* __restrict__ W2) {
    int i = blockIdx.x * blockDim.x + threadIdx.x;
    if (i >= HSZ * NC) return;
    int k = i / NC, n = i % NC;
    g_WencT[i] = (n < GSZ) ? encWhh[n * HSZ + k] : W1[(n - GSZ) * HSZ + k];
    g_WdecT[i] = (n < GSZ) ? decWhh[n * HSZ + k] : W2[(n - GSZ) * HSZ + k];
}
__global__ void wiht_kernel(const float* __restrict__ encWih, const float* __restrict__ decWih) {
    int i = blockIdx.x * blockDim.x + threadIdx.x;
    if (i >= ESZ * NB2) return;
    int k = i / NB2, n = i % NB2;
    g_WihT[i] = (n < GSZ) ? encWih[n * ESZ + k] : decWih[(n - GSZ) * ESZ + k];
}

// ---------- emb ----------
__global__ void emb_kernel(const float* __restrict__ inputs, const float* __restrict__ embW,
                           const float* __restrict__ embB) {
    int i = blockIdx.x * blockDim.x + threadIdx.x;
    if (i >= BSZ * SSZ * ESZ) return;
    int e = i % ESZ, bs = i / ESZ;
    float in0 = inputs[(size_t)bs * 2], in1 = inputs[(size_t)bs * 2 + 1];
    float mm = fmaf(in1, embW[2 * e + 1], __fmul_rn(in0, embW[2 * e]));
    g_emb[i] = __fadd_rn(mm, embB[e]);
}

// ---------- decoder step-0 input gates ----------
__global__ void xg0_kernel(const float* __restrict__ decWih, const float* __restrict__ dbih,
                           const float* __restrict__ dbhh, const float* __restrict__ dec0) {
    int n = blockIdx.x * blockDim.x + threadIdx.x;
    if (n >= GSZ) return;
    float acc = 0.f;
    for (int e = 0; e < ESZ; e++) acc = fmaf(dec0[e], decWih[n * ESZ + e], acc);
    g_xg0[n] = __fadd_rn(__fadd_rn(acc, dbih[n]), dbhh[n]);
}

// ---------- state init (also resets barrier state for each graph replay) ----------
__global__ void init_kernel(const float* __restrict__ h0, const float* __restrict__ c0,
                            const float* __restrict__ inputs) {
    int i = blockIdx.x * blockDim.x + threadIdx.x;
    if (i == 0) { g_barGen = 0; g_barCnt = 0; }
    if (i < BSZ * HSZ) {
        g_h[0][i] = h0[i & (HSZ - 1)];
        g_c[i]    = c0[i & (HSZ - 1)];
    }
    if (i < BSZ * SSZ) g_mask[i] = (inputs[(size_t)i * 2] > 0.0f) ? 1 : 0;
}

// ---------- xg precompute GEMM: [32768,4096] = emb @ WihT, fp32 ascending ----------
__global__ void __launch_bounds__(256) xg_gemm(const float* __restrict__ ebih, const float* __restrict__ ebhh,
                                               const float* __restrict__ dbih, const float* __restrict__ dbhh) {
    __shared__ __align__(16) float As[16][64 + 4];
    __shared__ __align__(16) float Bs[16][64];
    const int tid = threadIdx.x;
    const int row0 = blockIdx.y * 64;
    const int n0 = blockIdx.x * 64;
    const int lr = tid >> 2, lk = (tid & 3) << 2;
    const int bk = tid >> 4, bn = (tid & 15) << 2;
    const int tm = tid & 15, tn = tid >> 4;

    float acc[4][4];
#pragma unroll
    for (int i = 0; i < 4; i++)
#pragma unroll
        for (int j = 0; j < 4; j++) acc[i][j] = 0.f;

    {
        float4 av = *reinterpret_cast<const float4*>(g_emb + (size_t)(row0 + lr) * ESZ + lk);
        As[lk + 0][lr] = av.x; As[lk + 1][lr] = av.y;
        As[lk + 2][lr] = av.z; As[lk + 3][lr] = av.w;
        *reinterpret_cast<float4*>(&Bs[bk][bn]) =
            *reinterpret_cast<const float4*>(g_WihT + (size_t)bk * NB2 + n0 + bn);
    }
    __syncthreads();

    const int NKC = ESZ / 16;
    for (int kc = 0; kc < NKC; kc++) {
        float4 av; float4 bv;
        if (kc + 1 < NKC) {
            int k0 = (kc + 1) * 16;
            av = *reinterpret_cast<const float4*>(g_emb + (size_t)(row0 + lr) * ESZ + k0 + lk);
            bv = *reinterpret_cast<const float4*>(g_WihT + (size_t)(k0 + bk) * NB2 + n0 + bn);
        }
#pragma unroll
        for (int k = 0; k < 16; k++) {
            float4 a4 = *reinterpret_cast<const float4*>(&As[k][tm * 4]);
            float4 b4 = *reinterpret_cast<const float4*>(&Bs[k][tn * 4]);
            float ar[4] = {a4.x, a4.y, a4.z, a4.w};
            float br[4] = {b4.x, b4.y, b4.z, b4.w};
#pragma unroll
            for (int i = 0; i < 4; i++)
#pragma unroll
                for (int j = 0; j < 4; j++) acc[i][j] = fmaf(ar[i], br[j], acc[i][j]);
        }
        __syncthreads();
        if (kc + 1 < NKC) {
            As[lk + 0][lr] = av.x; As[lk + 1][lr] = av.y;
            As[lk + 2][lr] = av.z; As[lk + 3][lr] = av.w;
            *reinterpret_cast<float4*>(&Bs[bk][bn]) = bv;
            __syncthreads();
        }
    }

#pragma unroll
    for (int i = 0; i < 4; i++) {
        size_t row = row0 + tm * 4 + i;
#pragma unroll
        for (int j = 0; j < 4; j++) {
            int n = n0 + tn * 4 + j;
            if (n < GSZ)
                g_xg_enc[row * GSZ + n] = __fadd_rn(__fadd_rn(acc[i][j], ebih[n]), ebhh[n]);
            else {
                int nd = n - GSZ;
                g_xg_dec[row * GSZ + nd] = __fadd_rn(__fadd_rn(acc[i][j], dbih[nd]), dbhh[nd]);
            }
        }
    }
}

// ================= persistent kernel =================
#define BM 64
#define BN 80
#define BK 16

// software grid barrier: release(fence+atomic arrive) / acquire(volatile spin + fence)
__device__ __forceinline__ void grid_barrier(int epoch) {
    __syncthreads();
    if (threadIdx.x == 0) {
        __threadfence();
        int prev = atomicAdd(&g_barCnt, 1);
        if (prev == NBLK - 1) {
            g_barCnt = 0;
            __threadfence();
            atomicExch(&g_barGen, epoch);
        } else {
            while (*(volatile int*)&g_barGen < epoch) { __nanosleep(64); }
        }
        __threadfence();   // gpu-scope fence -> L1D invalidate; post-barrier loads coherent
    }
    __syncthreads();
}

struct SmemT {
    float As[BK][BM + 4];
    float Bs[BK][BN];
    float qs[HSZ];
    float Vs[HSZ];
    float us[SSZ];
    float es[SSZ];
    float ps[SSZ];
    float s_mx, s_sum;
    int   s_idx;
};

// GEMM phase: identical arithmetic to round-11 gemm_step
__device__ void dev_gemm(SmemT* sm, const float* __restrict__ A, const float* __restrict__ WT,
                         float* __restrict__ dst2, const float* __restrict__ bias2, int stride2,
                         int bx, int by) {
    const int tid = threadIdx.x;
    const int tm = tid & 15;
    const int tn = tid >> 4;
    const int row0 = by * BM;
    const int n0 = bx * BN;
    const int lr = tid >> 2, lk = (tid & 3) << 2;
    const int bk = tid >> 4, bn = tid & 15;

    float acc[4][5];
#pragma unroll
    for (int i = 0; i < 4; i++)
#pragma unroll
        for (int j = 0; j < 5; j++) acc[i][j] = 0.f;

    {
        float4 av = *reinterpret_cast<const float4*>(A + (size_t)(row0 + lr) * HSZ + lk);
        sm->As[lk + 0][lr] = av.x; sm->As[lk + 1][lr] = av.y;
        sm->As[lk + 2][lr] = av.z; sm->As[lk + 3][lr] = av.w;
#pragma unroll
        for (int j = 0; j < 5; j++)
            sm->Bs[bk][bn + 16 * j] = WT[(size_t)bk * NC + n0 + bn + 16 * j];
    }
    __syncthreads();

    const int NKC = HSZ / BK;  // 32
    for (int kc = 0; kc < NKC; kc++) {
        float4 av;
        float bv[5];
        if (kc + 1 < NKC) {
            int k0 = (kc + 1) * BK;
            av = *reinterpret_cast<const float4*>(A + (size_t)(row0 + lr) * HSZ + k0 + lk);
#pragma unroll
            for (int j = 0; j < 5; j++)
                bv[j] = WT[(size_t)(k0 + bk) * NC + n0 + bn + 16 * j];
        }
#pragma unroll
        for (int k = 0; k < BK; k++) {
            float4 a4 = *reinterpret_cast<const float4*>(&sm->As[k][tm * 4]);
            float ar[4] = {a4.x, a4.y, a4.z, a4.w};
            float br[5];
#pragma unroll
            for (int j = 0; j < 5; j++) br[j] = sm->Bs[k][tn + 16 * j];
#pragma unroll
            for (int i = 0; i < 4; i++)
#pragma unroll
                for (int j = 0; j < 5; j++) acc[i][j] = fmaf(ar[i], br[j], acc[i][j]);
        }
        __syncthreads();
        if (kc + 1 < NKC) {
            sm->As[lk + 0][lr] = av.x; sm->As[lk + 1][lr] = av.y;
            sm->As[lk + 2][lr] = av.z; sm->As[lk + 3][lr] = av.w;
#pragma unroll
            for (int j = 0; j < 5; j++) sm->Bs[bk][bn + 16 * j] = bv[j];
            __syncthreads();
        }
    }

#pragma unroll
    for (int i = 0; i < 4; i++) {
        int b = row0 + tm * 4 + i;
#pragma unroll
        for (int j = 0; j < 5; j++) {
            int n = n0 + tn + 16 * j;
            if (n < GSZ) {
                g_C[(size_t)b * GSZ + n] = acc[i][j];
            } else if (dst2) {
                int n2 = n - GSZ;
                dst2[(size_t)b * stride2 + n2] = __fadd_rn(acc[i][j], bias2[n2]);
            }
        }
    }
}

// cell phase (encoder + decoder t=0): identical per-element arithmetic
__device__ void dev_cell(float* __restrict__ h_out, const float* __restrict__ xg, size_t bstride) {
    int gtid = blockIdx.x * 256 + threadIdx.x;   // 0..32767
#pragma unroll
    for (int jj = 0; jj < 4; jj++) {
        int idx = gtid + 32768 * jj;
        int b = idx >> 9, hh = idx & (HSZ - 1);
        const float* Cb = g_C + (size_t)b * GSZ;
        const float* xr = xg + (size_t)b * bstride;
        float gi = __fadd_rn(xr[hh],           Cb[hh]);
        float gf = __fadd_rn(xr[HSZ + hh],     Cb[HSZ + hh]);
        float gg = __fadd_rn(xr[2 * HSZ + hh], Cb[2 * HSZ + hh]);
        float go = __fadd_rn(xr[3 * HSZ + hh], Cb[3 * HSZ + hh]);
        float si = sigf(gi), sf = sigf(gf), so = sigf(go);
        float tg = xtanh(gg);
        float cn = __fadd_rn(__fmul_rn(sf, g_c[idx]), __fmul_rn(si, tg));
        g_c[idx] = cn;
        h_out[idx] = __fmul_rn(so, xtanh(cn));
    }
}

// attention (+ optional fused decoder cell): block handles batches 2*bid, 2*bid+1
__device__ void dev_attn(SmemT* sm, int step, const float* __restrict__ V,
                         float* __restrict__ out_probs, float* __restrict__ out_idx,
                         float* __restrict__ h_out) {
    const int tid = threadIdx.x, lane = tid & 31, w = tid >> 5;
#pragma unroll 1
    for (int p = 0; p < 2; p++) {
        int b = 2 * blockIdx.x + p;
        for (int i = tid; i < HSZ; i += 256) {
            sm->qs[i] = g_q[(size_t)b * HSZ + i];
            sm->Vs[i] = V[i];
        }
        __syncthreads();

        // per-s dot: warp w does s = w + 8m (identical to round-10/11 arithmetic)
        for (int s = w; s < SSZ; s += 8) {
            const float* pr = g_proj + ((size_t)b * SSZ + s) * HSZ;
            float acc = 0.f;
            for (int h = lane; h < HSZ; h += 32)
                acc = fmaf(xtanh(__fadd_rn(pr[h], sm->qs[h])), sm->Vs[h], acc);
#pragma unroll
            for (int o = 16; o; o >>= 1)
                acc = __fadd_rn(acc, __shfl_xor_sync(0xffffffffu, acc, o));
            if (lane == 0) sm->us[s] = g_mask[b * SSZ + s] ? acc : -10000.0f;
        }
        __syncthreads();

        if (w == 0) {
            float mv = fmaxf(sm->us[lane], fmaxf(sm->us[lane + 32],
                       fmaxf(sm->us[lane + 64], sm->us[lane + 96])));
#pragma unroll
            for (int o = 16; o; o >>= 1) mv = fmaxf(mv, __shfl_xor_sync(0xffffffffu, mv, o));
            if (lane == 0) sm->s_mx = mv;
        }
        __syncthreads();

        if (tid < SSZ) sm->es[tid] = expf(__fadd_rn(sm->us[tid], -sm->s_mx));
        __syncthreads();

        if (w == 0) {
            float sv = __fadd_rn(__fadd_rn(sm->es[lane], sm->es[lane + 32]),
                                 __fadd_rn(sm->es[lane + 64], sm->es[lane + 96]));
#pragma unroll
            for (int o = 16; o; o >>= 1)
                sv = __fadd_rn(sv, __shfl_xor_sync(0xffffffffu, sv, o));
            if (lane == 0) sm->s_sum = sv;
        }
        __syncthreads();

        if (tid < SSZ) {
            float pp = __fdiv_rn(sm->es[tid], sm->s_sum);
            sm->ps[tid] = pp;
            out_probs[((size_t)step * BSZ + b) * SSZ + tid] = pp;
        }
        __syncthreads();

        if (w == 0) {
            float bv = -1.0f;
            int bi = 0;
#pragma unroll
            for (int k = 0; k < 4; k++) {
                int s = lane + 32 * k;
                float v = sm->ps[s];
                if (v > bv) { bv = v; bi = s; }
            }
#pragma unroll
            for (int o = 16; o; o >>= 1) {
                float ov = __shfl_xor_sync(0xffffffffu, bv, o);
                int oi = __shfl_xor_sync(0xffffffffu, bi, o);
                if (ov > bv || (ov == bv && oi < bi)) { bv = ov; bi = oi; }
            }
            if (lane == 0) sm->s_idx = bi;
        }
        __syncthreads();

        int bi = sm->s_idx;
        if (tid == 0) {
            g_mask[b * SSZ + bi] = 0;
            if (out_idx) out_idx[(size_t)b * SSZ + step] = (float)bi;
        }

        if (h_out && tid < 128) {
            const float* Cb = g_C + (size_t)b * GSZ;
            const float* xr = g_xg_dec + (size_t)b * ((size_t)SSZ * GSZ) + (size_t)bi * GSZ;
#pragma unroll
            for (int j = 0; j < 4; j++) {
                int hh = tid + 128 * j;
                int idx = b * HSZ + hh;
                float gi = __fadd_rn(xr[hh],           Cb[hh]);
                float gf = __fadd_rn(xr[HSZ + hh],     Cb[HSZ + hh]);
                float gg = __fadd_rn(xr[2 * HSZ + hh], Cb[2 * HSZ + hh]);
                float go = __fadd_rn(xr[3 * HSZ + hh], Cb[3 * HSZ + hh]);
                float si = sigf(gi), sf = sigf(gf), so = sigf(go);
                float tg = xtanh(gg);
                float cn = __fadd_rn(__fmul_rn(sf, g_c[idx]), __fmul_rn(si, tg));
                g_c[idx] = cn;
                h_out[idx] = __fmul_rn(so, xtanh(cn));
            }
        }
        __syncthreads();
    }
}

__global__ void __launch_bounds__(256) persistent_kernel(const float* __restrict__ b1,
                                                         const float* __restrict__ b2,
                                                         const float* __restrict__ V,
                                                         float* __restrict__ out_probs,
                                                         float* __restrict__ out_idx) {
    __shared__ SmemT sm;
    const int bx = blockIdx.x & 31, by = blockIdx.x >> 5;
    float* hbuf[2] = {g_h[0], g_h[1]};
    int cur = 0;
    int ep = 0;

    // -------- encoder --------
    for (int t = 0; t < SSZ; t++) {
        dev_gemm(&sm, hbuf[cur], g_WencT,
                 (t > 0) ? (g_proj + (size_t)(t - 1) * HSZ) : nullptr,
                 b1, SSZ * HSZ, bx, by);
        grid_barrier(++ep);
        dev_cell(hbuf[cur ^ 1], g_xg_enc + (size_t)t * GSZ, (size_t)SSZ * GSZ);
        grid_barrier(++ep);
        cur ^= 1;
    }
    dev_gemm(&sm, hbuf[cur], g_WencT, g_proj + (size_t)(SSZ - 1) * HSZ, b1, SSZ * HSZ, bx, by);
    grid_barrier(++ep);

    // -------- decoder --------
    for (int t = 0; t < SSZ; t++) {
        dev_gemm(&sm, hbuf[cur], g_WdecT, (t > 0) ? g_q : nullptr, b2, HSZ, bx, by);
        grid_barrier(++ep);
        if (t == 0) {
            dev_cell(hbuf[cur ^ 1], g_xg0, 0);
        } else {
            dev_attn(&sm, t - 1, V, out_probs, out_idx, hbuf[cur ^ 1]);
        }
        grid_barrier(++ep);
        cur ^= 1;
    }
    dev_gemm(&sm, hbuf[cur], g_WdecT, g_q, b2, HSZ, bx, by);
    grid_barrier(++ep);
    dev_attn(&sm, SSZ - 1, V, out_probs, out_idx, nullptr);
}

// ---------- host ----------
extern "C" void kernel_launch(void* const* d_in, const int* in_sizes, int n_in,
                              void* d_out, int out_size) {
    const float* inputs  = (const float*)d_in[0];
    const float* emb_W   = (const float*)d_in[2];
    const float* emb_b   = (const float*)d_in[3];
    const float* enc_Wih = (const float*)d_in[4];
    const float* enc_Whh = (const float*)d_in[5];
    const float* enc_bih = (const float*)d_in[6];
    const float* enc_bhh = (const float*)d_in[7];
    const float* h0      = (const float*)d_in[8];
    const float* c0      = (const float*)d_in[9];
    const float* dec0    = (const float*)d_in[10];
    const float* dec_Wih = (const float*)d_in[11];
    const float* dec_Whh = (const float*)d_in[12];
    const float* dec_bih = (const float*)d_in[13];
    const float* dec_bhh = (const float*)d_in[14];
    const float* W1      = (const float*)d_in[15];
    const float* b1      = (const float*)d_in[16];
    const float* W2      = (const float*)d_in[17];
    const float* b2      = (const float*)d_in[18];
    const float* V       = (const float*)d_in[19];

    transpose_kernel<<<(HSZ * NC + 255) / 256, 256>>>(enc_Whh, W1, dec_Whh, W2);
    wiht_kernel<<<(ESZ * NB2 + 255) / 256, 256>>>(enc_Wih, dec_Wih);
    emb_kernel<<<(BSZ * SSZ * ESZ + 255) / 256, 256>>>(inputs, emb_W, emb_b);
    xg0_kernel<<<GSZ / 256, 256>>>(dec_Wih, dec_bih, dec_bhh, dec0);
    init_kernel<<<(BSZ * HSZ + 255) / 256, 256>>>(h0, c0, inputs);
    {
        dim3 gx(NB2 / 64, BSZ * SSZ / 64);
        xg_gemm<<<gx, 256>>>(enc_bih, enc_bhh, dec_bih, dec_bhh);
    }

    float* out_probs = (float*)d_out;
    const size_t PROBS_N = (size_t)SSZ * BSZ * SSZ;
    float* out_idx = ((size_t)out_size >= PROBS_N + (size_t)BSZ * SSZ)
                         ? out_probs + PROBS_N : nullptr;

    persistent_kernel<<<NBLK, 256>>>(b1, b2, V, out_probs, out_idx);
}

// round 13
// speedup vs baseline: 1.4651x; 1.4651x over previous
#include <cuda_runtime.h>
#include <math.h>
#include <stddef.h>

#define BSZ 256
#define SSZ 128
#define ESZ 256
#define HSZ 512
#define GSZ 2048   // 4*H
#define NC  2560   // 2048 interleaved gates + 512 (proj or q)
#define NB2 4096   // 2*GSZ combined xg cols

// ---------- device scratch ----------
__device__ float  g_WencT[HSZ * NC];
__device__ float  g_WdecT[HSZ * NC];
__device__ float  g_WihT[ESZ * NB2];
__device__ float  g_emb[(size_t)BSZ * SSZ * ESZ];
__device__ float  g_xg_enc[(size_t)BSZ * SSZ * GSZ];   // interleaved gate cols
__device__ float  g_xg_dec[(size_t)BSZ * SSZ * GSZ];   // interleaved gate cols
__device__ float  g_proj[(size_t)BSZ * SSZ * HSZ];
__device__ float  g_C[BSZ * GSZ];                       // interleaved gate cols
__device__ float  g_h[2][BSZ * HSZ];
__device__ float  g_c[BSZ * HSZ];
__device__ float  g_q[BSZ * HSZ];
__device__ float  g_xg0[GSZ];                           // interleaved
__device__ int    g_mask[BSZ * SSZ];

// ---------- frozen numerics: libdevice tanh, exp-based logistic ----------
__device__ __forceinline__ float xtanh(float x) { return tanhf(x); }
__device__ __forceinline__ float sigf(float x) {
    return __fdiv_rn(1.0f, __fadd_rn(1.0f, expf(-x)));
}

// interleaved col n (<2048)  ->  original gate row (g*512+hh)
__device__ __forceinline__ int deint(int n) { return (n & 3) * HSZ + (n >> 2); }

// ---------- weight transposes (gate cols interleaved) ----------
__global__ void transpose_kernel(const float* __restrict__ encWhh, const float* __restrict__ W1,
                                 const float* __restrict__ decWhh, const float* __restrict__ W2) {
    int i = blockIdx.x * blockDim.x + threadIdx.x;
    if (i >= HSZ * NC) return;
    int k = i / NC, n = i % NC;
    float v, w;
    if (n < GSZ) {
        int orig = deint(n);
        v = encWhh[orig * HSZ + k];
        w = decWhh[orig * HSZ + k];
    } else {
        v = W1[(n - GSZ) * HSZ + k];
        w = W2[(n - GSZ) * HSZ + k];
    }
    g_WencT[i] = v;
    g_WdecT[i] = w;
}
__global__ void wiht_kernel(const float* __restrict__ encWih, const float* __restrict__ decWih) {
    int i = blockIdx.x * blockDim.x + threadIdx.x;
    if (i >= ESZ * NB2) return;
    int k = i / NB2, n = i % NB2;
    float v;
    if (n < GSZ) v = encWih[deint(n) * ESZ + k];
    else         v = decWih[deint(n - GSZ) * ESZ + k];
    g_WihT[i] = v;
}

// ---------- emb ----------
__global__ void emb_kernel(const float* __restrict__ inputs, const float* __restrict__ embW,
                           const float* __restrict__ embB) {
    int i = blockIdx.x * blockDim.x + threadIdx.x;
    if (i >= BSZ * SSZ * ESZ) return;
    int e = i % ESZ, bs = i / ESZ;
    float in0 = inputs[(size_t)bs * 2], in1 = inputs[(size_t)bs * 2 + 1];
    float mm = fmaf(in1, embW[2 * e + 1], __fmul_rn(in0, embW[2 * e]));
    g_emb[i] = __fadd_rn(mm, embB[e]);
}

// ---------- decoder step-0 input gates (interleaved output) ----------
__global__ void xg0_kernel(const float* __restrict__ decWih, const float* __restrict__ dbih,
                           const float* __restrict__ dbhh, const float* __restrict__ dec0) {
    int n = blockIdx.x * blockDim.x + threadIdx.x;
    if (n >= GSZ) return;
    int orig = deint(n);
    float acc = 0.f;
    for (int e = 0; e < ESZ; e++) acc = fmaf(dec0[e], decWih[orig * ESZ + e], acc);
    g_xg0[n] = __fadd_rn(__fadd_rn(acc, dbih[orig]), dbhh[orig]);
}

// ---------- state init ----------
__global__ void init_kernel(const float* __restrict__ h0, const float* __restrict__ c0,
                            const float* __restrict__ inputs) {
    int i = blockIdx.x * blockDim.x + threadIdx.x;
    if (i < BSZ * HSZ) {
        g_h[0][i] = h0[i & (HSZ - 1)];
        g_c[i]    = c0[i & (HSZ - 1)];
    }
    if (i < BSZ * SSZ) g_mask[i] = (inputs[(size_t)i * 2] > 0.0f) ? 1 : 0;
}

// ---------- xg precompute GEMM: [32768,4096] = emb @ WihT (interleaved cols) ----------
__global__ void __launch_bounds__(256) xg_gemm(const float* __restrict__ ebih, const float* __restrict__ ebhh,
                                               const float* __restrict__ dbih, const float* __restrict__ dbhh) {
    __shared__ __align__(16) float As[16][64 + 4];
    __shared__ __align__(16) float Bs[16][64];
    const int tid = threadIdx.x;
    const int row0 = blockIdx.y * 64;
    const int n0 = blockIdx.x * 64;
    const int lr = tid >> 2, lk = (tid & 3) << 2;
    const int bk = tid >> 4, bn = (tid & 15) << 2;
    const int tm = tid & 15, tn = tid >> 4;

    float acc[4][4];
#pragma unroll
    for (int i = 0; i < 4; i++)
#pragma unroll
        for (int j = 0; j < 4; j++) acc[i][j] = 0.f;

    {
        float4 av = *reinterpret_cast<const float4*>(g_emb + (size_t)(row0 + lr) * ESZ + lk);
        As[lk + 0][lr] = av.x; As[lk + 1][lr] = av.y;
        As[lk + 2][lr] = av.z; As[lk + 3][lr] = av.w;
        *reinterpret_cast<float4*>(&Bs[bk][bn]) =
            *reinterpret_cast<const float4*>(g_WihT + (size_t)bk * NB2 + n0 + bn);
    }
    __syncthreads();

    const int NKC = ESZ / 16;
    for (int kc = 0; kc < NKC; kc++) {
        float4 av; float4 bv;
        if (kc + 1 < NKC) {
            int k0 = (kc + 1) * 16;
            av = *reinterpret_cast<const float4*>(g_emb + (size_t)(row0 + lr) * ESZ + k0 + lk);
            bv = *reinterpret_cast<const float4*>(g_WihT + (size_t)(k0 + bk) * NB2 + n0 + bn);
        }
#pragma unroll
        for (int k = 0; k < 16; k++) {
            float4 a4 = *reinterpret_cast<const float4*>(&As[k][tm * 4]);
            float4 b4 = *reinterpret_cast<const float4*>(&Bs[k][tn * 4]);
            float ar[4] = {a4.x, a4.y, a4.z, a4.w};
            float br[4] = {b4.x, b4.y, b4.z, b4.w};
#pragma unroll
            for (int i = 0; i < 4; i++)
#pragma unroll
                for (int j = 0; j < 4; j++) acc[i][j] = fmaf(ar[i], br[j], acc[i][j]);
        }
        __syncthreads();
        if (kc + 1 < NKC) {
            As[lk + 0][lr] = av.x; As[lk + 1][lr] = av.y;
            As[lk + 2][lr] = av.z; As[lk + 3][lr] = av.w;
            *reinterpret_cast<float4*>(&Bs[bk][bn]) = bv;
            __syncthreads();
        }
    }

#pragma unroll
    for (int i = 0; i < 4; i++) {
        size_t row = row0 + tm * 4 + i;
#pragma unroll
        for (int j = 0; j < 4; j++) {
            int n = n0 + tn * 4 + j;
            if (n < GSZ) {
                int orig = deint(n);
                g_xg_enc[row * GSZ + n] = __fadd_rn(__fadd_rn(acc[i][j], ebih[orig]), ebhh[orig]);
            } else {
                int nd = n - GSZ;
                int orig = deint(nd);
                g_xg_dec[row * GSZ + nd] = __fadd_rn(__fadd_rn(acc[i][j], dbih[orig]), dbhh[orig]);
            }
        }
    }
}

// ---------- fused step GEMM (+ optional fused LSTM cell in epilogue) ----------
#define BM 64
#define BN 80
#define BK 16
__global__ void __launch_bounds__(256) gemm_step(const float* __restrict__ A,
                                                 const float* __restrict__ WT,
                                                 float* __restrict__ dst2,
                                                 const float* __restrict__ bias2,
                                                 int stride2,
                                                 int do_cell,
                                                 const float* __restrict__ xg,
                                                 size_t bstride,
                                                 float* __restrict__ h_out) {
    __shared__ __align__(16) float As[BK][BM + 4];
    __shared__ __align__(16) float Bs[BK][BN];
    __shared__ __align__(16) float Cs[BM][BN];

    const int tid = threadIdx.x;
    const int tm = tid & 15;
    const int tn = tid >> 4;
    const int row0 = blockIdx.y * BM;
    const int n0 = blockIdx.x * BN;
    const int lr = tid >> 2, lk = (tid & 3) << 2;
    const int bk = tid >> 4, bn = tid & 15;

    float acc[4][5];
#pragma unroll
    for (int i = 0; i < 4; i++)
#pragma unroll
        for (int j = 0; j < 5; j++) acc[i][j] = 0.f;

    {
        float4 av = *reinterpret_cast<const float4*>(A + (size_t)(row0 + lr) * HSZ + lk);
        As[lk + 0][lr] = av.x; As[lk + 1][lr] = av.y;
        As[lk + 2][lr] = av.z; As[lk + 3][lr] = av.w;
#pragma unroll
        for (int j = 0; j < 5; j++)
            Bs[bk][bn + 16 * j] = WT[(size_t)bk * NC + n0 + bn + 16 * j];
    }
    __syncthreads();

    const int NKC = HSZ / BK;  // 32
    for (int kc = 0; kc < NKC; kc++) {
        float4 av;
        float bv[5];
        if (kc + 1 < NKC) {
            int k0 = (kc + 1) * BK;
            av = *reinterpret_cast<const float4*>(A + (size_t)(row0 + lr) * HSZ + k0 + lk);
#pragma unroll
            for (int j = 0; j < 5; j++)
                bv[j] = WT[(size_t)(k0 + bk) * NC + n0 + bn + 16 * j];
        }
#pragma unroll
        for (int k = 0; k < BK; k++) {
            float4 a4 = *reinterpret_cast<const float4*>(&As[k][tm * 4]);
            float ar[4] = {a4.x, a4.y, a4.z, a4.w};
            float br[5];
#pragma unroll
            for (int j = 0; j < 5; j++) br[j] = Bs[k][tn + 16 * j];
#pragma unroll
            for (int i = 0; i < 4; i++)
#pragma unroll
                for (int j = 0; j < 5; j++) acc[i][j] = fmaf(ar[i], br[j], acc[i][j]);
        }
        __syncthreads();
        if (kc + 1 < NKC) {
            As[lk + 0][lr] = av.x; As[lk + 1][lr] = av.y;
            As[lk + 2][lr] = av.z; As[lk + 3][lr] = av.w;
#pragma unroll
            for (int j = 0; j < 5; j++) Bs[bk][bn + 16 * j] = bv[j];
            __syncthreads();
        }
    }

    // ---- epilogue ----
#pragma unroll
    for (int i = 0; i < 4; i++) {
        int b = row0 + tm * 4 + i;
#pragma unroll
        for (int j = 0; j < 5; j++) {
            int n = n0 + tn + 16 * j;
            if (n < GSZ) {
                if (do_cell) Cs[tm * 4 + i][tn + 16 * j] = acc[i][j];
                else         g_C[(size_t)b * GSZ + n] = acc[i][j];
            } else if (dst2) {
                int n2 = n - GSZ;
                dst2[(size_t)b * stride2 + n2] = __fadd_rn(acc[i][j], bias2[n2]);
            }
        }
    }

    if (do_cell) {
        __syncthreads();
        int gate_cols = (n0 < GSZ) ? min(GSZ - n0, BN) : 0;
        int nquads = gate_cols >> 2;          // 20, or 12 for the boundary block, or 0
        int items = BM * nquads;
        for (int it = tid; it < items; it += 256) {
            int r = it / nquads, qi = it - r * nquads;
            int b = row0 + r;
            int hh = (n0 >> 2) + qi;
            const float* xr = xg + (size_t)b * bstride + n0 + 4 * qi;
            int c4 = 4 * qi;
            float gi = __fadd_rn(xr[0], Cs[r][c4 + 0]);
            float gf = __fadd_rn(xr[1], Cs[r][c4 + 1]);
            float gg = __fadd_rn(xr[2], Cs[r][c4 + 2]);
            float go = __fadd_rn(xr[3], Cs[r][c4 + 3]);
            float si = sigf(gi), sf = sigf(gf), so = sigf(go);
            float tg = xtanh(gg);
            int idx = b * HSZ + hh;
            float cn = __fadd_rn(__fmul_rn(sf, g_c[idx]), __fmul_rn(si, tg));
            g_c[idx] = cn;
            h_out[idx] = __fmul_rn(so, xtanh(cn));
        }
    }
}

// ---------- fused attention: dots + softmax + argmax + mask + decoder cell ----------
// 256 blocks x 512 threads; warp w computes s = w + 16m (identical per-s arithmetic).
__global__ void __launch_bounds__(512) attn_kernel(int step,
                                                   const float* __restrict__ V,
                                                   float* __restrict__ out_probs,
                                                   float* __restrict__ out_idx,
                                                   float* __restrict__ h_out) {
    int b = blockIdx.x;
    int tid = threadIdx.x, lane = tid & 31, w = tid >> 5;
    __shared__ float qs[HSZ];
    __shared__ float Vs[HSZ];
    __shared__ float us[SSZ];
    __shared__ float es[SSZ];
    __shared__ float ps[SSZ];
    __shared__ float s_mx, s_sum;
    __shared__ int s_idx;

    for (int i = tid; i < HSZ; i += 512) {
        qs[i] = g_q[(size_t)b * HSZ + i];
        Vs[i] = V[i];
    }
    __syncthreads();

#pragma unroll
    for (int m = 0; m < 8; m++) {
        int s = w + 16 * m;
        const float* pr = g_proj + ((size_t)b * SSZ + s) * HSZ;
        float acc = 0.f;
        for (int h = lane; h < HSZ; h += 32)
            acc = fmaf(xtanh(__fadd_rn(pr[h], qs[h])), Vs[h], acc);
#pragma unroll
        for (int o = 16; o; o >>= 1)
            acc = __fadd_rn(acc, __shfl_xor_sync(0xffffffffu, acc, o));
        if (lane == 0) us[s] = g_mask[b * SSZ + s] ? acc : -10000.0f;
    }
    __syncthreads();

    if (w == 0) {
        float mv = fmaxf(us[lane], fmaxf(us[lane + 32], fmaxf(us[lane + 64], us[lane + 96])));
#pragma unroll
        for (int o = 16; o; o >>= 1) mv = fmaxf(mv, __shfl_xor_sync(0xffffffffu, mv, o));
        if (lane == 0) s_mx = mv;
    }
    __syncthreads();

    if (tid < SSZ) es[tid] = expf(__fadd_rn(us[tid], -s_mx));
    __syncthreads();

    if (w == 0) {
        float sv = __fadd_rn(__fadd_rn(es[lane], es[lane + 32]),
                             __fadd_rn(es[lane + 64], es[lane + 96]));
#pragma unroll
        for (int o = 16; o; o >>= 1)
            sv = __fadd_rn(sv, __shfl_xor_sync(0xffffffffu, sv, o));
        if (lane == 0) s_sum = sv;
    }
    __syncthreads();

    if (tid < SSZ) {
        float p = __fdiv_rn(es[tid], s_sum);
        ps[tid] = p;
        out_probs[((size_t)step * BSZ + b) * SSZ + tid] = p;
    }
    __syncthreads();

    if (w == 0) {
        float bv = -1.0f;
        int bi = 0;
#pragma unroll
        for (int k = 0; k < 4; k++) {
            int s = lane + 32 * k;
            float v = ps[s];
            if (v > bv) { bv = v; bi = s; }
        }
#pragma unroll
        for (int o = 16; o; o >>= 1) {
            float ov = __shfl_xor_sync(0xffffffffu, bv, o);
            int oi = __shfl_xor_sync(0xffffffffu, bi, o);
            if (ov > bv || (ov == bv && oi < bi)) { bv = ov; bi = oi; }
        }
        if (lane == 0) s_idx = bi;
    }
    __syncthreads();

    int bi = s_idx;
    if (tid == 0) {
        g_mask[b * SSZ + bi] = 0;
        if (out_idx) out_idx[(size_t)b * SSZ + step] = (float)bi;
    }

    // fused decoder cell (interleaved gate layout in g_C and g_xg_dec)
    if (h_out && tid < 128) {
        const float* Cb = g_C + (size_t)b * GSZ;
        const float* xr = g_xg_dec + ((size_t)b * SSZ + bi) * GSZ;
#pragma unroll
        for (int j = 0; j < 4; j++) {
            int hh = tid + 128 * j;
            int n4 = 4 * hh;
            int idx = b * HSZ + hh;
            float gi = __fadd_rn(xr[n4 + 0], Cb[n4 + 0]);
            float gf = __fadd_rn(xr[n4 + 1], Cb[n4 + 1]);
            float gg = __fadd_rn(xr[n4 + 2], Cb[n4 + 2]);
            float go = __fadd_rn(xr[n4 + 3], Cb[n4 + 3]);
            float si = sigf(gi), sf = sigf(gf), so = sigf(go);
            float tg = xtanh(gg);
            float cn = __fadd_rn(__fmul_rn(sf, g_c[idx]), __fmul_rn(si, tg));
            g_c[idx] = cn;
            h_out[idx] = __fmul_rn(so, xtanh(cn));
        }
    }
}

// ---------- host ----------
extern "C" void kernel_launch(void* const* d_in, const int* in_sizes, int n_in,
                              void* d_out, int out_size) {
    const float* inputs  = (const float*)d_in[0];
    const float* emb_W   = (const float*)d_in[2];
    const float* emb_b   = (const float*)d_in[3];
    const float* enc_Wih = (const float*)d_in[4];
    const float* enc_Whh = (const float*)d_in[5];
    const float* enc_bih = (const float*)d_in[6];
    const float* enc_bhh = (const float*)d_in[7];
    const float* h0      = (const float*)d_in[8];
    const float* c0      = (const float*)d_in[9];
    const float* dec0    = (const float*)d_in[10];
    const float* dec_Wih = (const float*)d_in[11];
    const float* dec_Whh = (const float*)d_in[12];
    const float* dec_bih = (const float*)d_in[13];
    const float* dec_bhh = (const float*)d_in[14];
    const float* W1      = (const float*)d_in[15];
    const float* b1      = (const float*)d_in[16];
    const float* W2      = (const float*)d_in[17];
    const float* b2      = (const float*)d_in[18];
    const float* V       = (const float*)d_in[19];

    float *pWencT, *pWdecT, *pproj, *pq, *ph, *pxg_enc, *pxg0;
    cudaGetSymbolAddress((void**)&pWencT,  g_WencT);
    cudaGetSymbolAddress((void**)&pWdecT,  g_WdecT);
    cudaGetSymbolAddress((void**)&pproj,   g_proj);
    cudaGetSymbolAddress((void**)&pq,      g_q);
    cudaGetSymbolAddress((void**)&ph,      g_h);
    cudaGetSymbolAddress((void**)&pxg_enc, g_xg_enc);
    cudaGetSymbolAddress((void**)&pxg0,    g_xg0);
    float* hbuf[2] = {ph, ph + BSZ * HSZ};

    transpose_kernel<<<(HSZ * NC + 255) / 256, 256>>>(enc_Whh, W1, dec_Whh, W2);
    wiht_kernel<<<(ESZ * NB2 + 255) / 256, 256>>>(enc_Wih, dec_Wih);
    emb_kernel<<<(BSZ * SSZ * ESZ + 255) / 256, 256>>>(inputs, emb_W, emb_b);
    xg0_kernel<<<GSZ / 256, 256>>>(dec_Wih, dec_bih, dec_bhh, dec0);
    init_kernel<<<(BSZ * HSZ + 255) / 256, 256>>>(h0, c0, inputs);
    {
        dim3 gx(NB2 / 64, BSZ * SSZ / 64);
        xg_gemm<<<gx, 256>>>(enc_bih, enc_bhh, dec_bih, dec_bhh);
    }

    float* out_probs = (float*)d_out;
    const size_t PROBS_N = (size_t)SSZ * BSZ * SSZ;
    float* out_idx = ((size_t)out_size >= PROBS_N + (size_t)BSZ * SSZ)
                         ? out_probs + PROBS_N : nullptr;

    dim3 gg(NC / BN, BSZ / BM);     // 32 x 4 = 128 blocks
    const size_t XB = (size_t)SSZ * GSZ;
    int cur = 0;

    // encoder: gemm (+cell fused) per step
    for (int t = 0; t < SSZ; t++) {
        gemm_step<<<gg, 256>>>(hbuf[cur], pWencT,
                               (t > 0) ? (pproj + (size_t)(t - 1) * HSZ) : nullptr,
                               b1, SSZ * HSZ,
                               1, pxg_enc + (size_t)t * GSZ, XB, hbuf[cur ^ 1]);
        cur ^= 1;
    }
    // proj tail for the final encoder output (no cell)
    gemm_step<<<gg, 256>>>(hbuf[cur], pWencT, pproj + (size_t)(SSZ - 1) * HSZ, b1, SSZ * HSZ,
                           0, nullptr, 0, nullptr);

    // decoder
    for (int t = 0; t < SSZ; t++) {
        if (t == 0) {
            // gates(0) + cell fused (xg0); no q needed yet
            gemm_step<<<gg, 256>>>(hbuf[cur], pWdecT, nullptr, b2, HSZ,
                                   1, pxg0, 0, hbuf[cur ^ 1]);
        } else {
            // gates(t) to g_C + q for attention(t-1); attn does softmax/argmax + cell(t)
            gemm_step<<<gg, 256>>>(hbuf[cur], pWdecT, pq, b2, HSZ,
                                   0, nullptr, 0, nullptr);
            attn_kernel<<<BSZ, 512>>>(t - 1, V, out_probs, out_idx, hbuf[cur ^ 1]);
        }
        cur ^= 1;
    }
    // final q + attention for step S-1 (no cell)
    gemm_step<<<gg, 256>>>(hbuf[cur], pWdecT, pq, b2, HSZ, 0, nullptr, 0, nullptr);
    attn_kernel<<<BSZ, 512>>>(SSZ - 1, V, out_probs, out_idx, nullptr);
}

// round 14
// speedup vs baseline: 1.7252x; 1.1775x over previous
#include <cuda_runtime.h>
#include <math.h>
#include <stddef.h>

#define BSZ 256
#define SSZ 128
#define ESZ 256
#define HSZ 512
#define GSZ 2048   // 4*H (interleaved gate cols)
#define NC  2560   // decoder: 2048 interleaved gates + 512 (q)
#define NB2 4096

// ---------- device scratch ----------
__device__ float  g_WencG[HSZ * GSZ];                   // enc Whh^T, interleaved gate cols
__device__ float  g_W1T[HSZ * HSZ];
__device__ float  g_WdecT[HSZ * NC];                    // dec Whh^T interleaved | W2^T
__device__ float  g_WihT[ESZ * NB2];
__device__ float  g_emb[(size_t)BSZ * SSZ * ESZ];
__device__ float  g_xg_enc[(size_t)BSZ * SSZ * GSZ];
__device__ float  g_xg_dec[(size_t)BSZ * SSZ * GSZ];
__device__ float  g_proj[(size_t)BSZ * SSZ * HSZ];
__device__ float  g_hall[(size_t)(SSZ + 1) * BSZ * HSZ]; // encoder h states [t][b][h]
__device__ float  g_hdec[BSZ * HSZ];
__device__ float  g_C[BSZ * GSZ];                       // interleaved
__device__ float  g_c[BSZ * HSZ];
__device__ float  g_q[BSZ * HSZ];
__device__ float  g_xg0[GSZ];                           // interleaved
__device__ float  g_us[BSZ * SSZ];
__device__ int    g_mask[BSZ * SSZ];

// ---------- frozen numerics ----------
__device__ __forceinline__ float xtanh(float x) { return tanhf(x); }
__device__ __forceinline__ float sigf(float x) {
    return __fdiv_rn(1.0f, __fadd_rn(1.0f, expf(-x)));
}
__device__ __forceinline__ int deint(int n) { return (n & 3) * HSZ + (n >> 2); }

// ---------- state init ----------
__global__ void init_kernel(const float* __restrict__ h0, const float* __restrict__ c0,
                            const float* __restrict__ inputs) {
    int i = blockIdx.x * blockDim.x + threadIdx.x;
    if (i < BSZ * HSZ) {
        g_hall[i] = h0[i & (HSZ - 1)];
        g_c[i]    = c0[i & (HSZ - 1)];
    }
    if (i < BSZ * SSZ) g_mask[i] = (inputs[(size_t)i * 2] > 0.0f) ? 1 : 0;
}

// ---------- weight transposes ----------
__global__ void transpose_kernel(const float* __restrict__ encWhh, const float* __restrict__ W1,
                                 const float* __restrict__ decWhh, const float* __restrict__ W2) {
    int i = blockIdx.x * blockDim.x + threadIdx.x;
    if (i >= HSZ * NC) return;
    int k = i / NC, n = i % NC;
    if (n < GSZ) {
        int orig = deint(n);
        g_WencG[k * GSZ + n] = encWhh[orig * HSZ + k];
        g_WdecT[i] = decWhh[orig * HSZ + k];
    } else {
        int n2 = n - GSZ;
        g_W1T[k * HSZ + n2] = W1[n2 * HSZ + k];
        g_WdecT[i] = W2[n2 * HSZ + k];
    }
}
__global__ void wiht_kernel(const float* __restrict__ encWih, const float* __restrict__ decWih) {
    int i = blockIdx.x * blockDim.x + threadIdx.x;
    if (i >= ESZ * NB2) return;
    int k = i / NB2, n = i % NB2;
    float v;
    if (n < GSZ) v = encWih[deint(n) * ESZ + k];
    else         v = decWih[deint(n - GSZ) * ESZ + k];
    g_WihT[i] = v;
}

// ---------- emb ----------
__global__ void emb_kernel(const float* __restrict__ inputs, const float* __restrict__ embW,
                           const float* __restrict__ embB) {
    int i = blockIdx.x * blockDim.x + threadIdx.x;
    if (i >= BSZ * SSZ * ESZ) return;
    int e = i % ESZ, bs = i / ESZ;
    float in0 = inputs[(size_t)bs * 2], in1 = inputs[(size_t)bs * 2 + 1];
    float mm = fmaf(in1, embW[2 * e + 1], __fmul_rn(in0, embW[2 * e]));
    g_emb[i] = __fadd_rn(mm, embB[e]);
}

// ---------- decoder step-0 input gates (interleaved) ----------
__global__ void xg0_kernel(const float* __restrict__ decWih, const float* __restrict__ dbih,
                           const float* __restrict__ dbhh, const float* __restrict__ dec0) {
    int n = blockIdx.x * blockDim.x + threadIdx.x;
    if (n >= GSZ) return;
    int orig = deint(n);
    float acc = 0.f;
    for (int e = 0; e < ESZ; e++) acc = fmaf(dec0[e], decWih[orig * ESZ + e], acc);
    g_xg0[n] = __fadd_rn(__fadd_rn(acc, dbih[orig]), dbhh[orig]);
}

// ---------- xg precompute GEMM ----------
__global__ void __launch_bounds__(256) xg_gemm(const float* __restrict__ ebih, const float* __restrict__ ebhh,
                                               const float* __restrict__ dbih, const float* __restrict__ dbhh) {
    __shared__ __align__(16) float As[16][64 + 4];
    __shared__ __align__(16) float Bs[16][64];
    const int tid = threadIdx.x;
    const int row0 = blockIdx.y * 64;
    const int n0 = blockIdx.x * 64;
    const int lr = tid >> 2, lk = (tid & 3) << 2;
    const int bk = tid >> 4, bn = (tid & 15) << 2;
    const int tm = tid & 15, tn = tid >> 4;

    float acc[4][4];
#pragma unroll
    for (int i = 0; i < 4; i++)
#pragma unroll
        for (int j = 0; j < 4; j++) acc[i][j] = 0.f;

    {
        float4 av = *reinterpret_cast<const float4*>(g_emb + (size_t)(row0 + lr) * ESZ + lk);
        As[lk + 0][lr] = av.x; As[lk + 1][lr] = av.y;
        As[lk + 2][lr] = av.z; As[lk + 3][lr] = av.w;
        *reinterpret_cast<float4*>(&Bs[bk][bn]) =
            *reinterpret_cast<const float4*>(g_WihT + (size_t)bk * NB2 + n0 + bn);
    }
    __syncthreads();

    const int NKC = ESZ / 16;
    for (int kc = 0; kc < NKC; kc++) {
        float4 av; float4 bv;
        if (kc + 1 < NKC) {
            int k0 = (kc + 1) * 16;
            av = *reinterpret_cast<const float4*>(g_emb + (size_t)(row0 + lr) * ESZ + k0 + lk);
            bv = *reinterpret_cast<const float4*>(g_WihT + (size_t)(k0 + bk) * NB2 + n0 + bn);
        }
#pragma unroll
        for (int k = 0; k < 16; k++) {
            float4 a4 = *reinterpret_cast<const float4*>(&As[k][tm * 4]);
            float4 b4 = *reinterpret_cast<const float4*>(&Bs[k][tn * 4]);
            float ar[4] = {a4.x, a4.y, a4.z, a4.w};
            float br[4] = {b4.x, b4.y, b4.z, b4.w};
#pragma unroll
            for (int i = 0; i < 4; i++)
#pragma unroll
                for (int j = 0; j < 4; j++) acc[i][j] = fmaf(ar[i], br[j], acc[i][j]);
        }
        __syncthreads();
        if (kc + 1 < NKC) {
            As[lk + 0][lr] = av.x; As[lk + 1][lr] = av.y;
            As[lk + 2][lr] = av.z; As[lk + 3][lr] = av.w;
            *reinterpret_cast<float4*>(&Bs[bk][bn]) = bv;
            __syncthreads();
        }
    }

#pragma unroll
    for (int i = 0; i < 4; i++) {
        size_t row = row0 + tm * 4 + i;
#pragma unroll
        for (int j = 0; j < 4; j++) {
            int n = n0 + tn * 4 + j;
            if (n < GSZ) {
                int orig = deint(n);
                g_xg_enc[row * GSZ + n] = __fadd_rn(__fadd_rn(acc[i][j], ebih[orig]), ebhh[orig]);
            } else {
                int nd = n - GSZ;
                int orig = deint(nd);
                g_xg_dec[row * GSZ + nd] = __fadd_rn(__fadd_rn(acc[i][j], dbih[orig]), dbhh[orig]);
            }
        }
    }
}

// ---------- encoder step GEMM [256,2048] = h @ WencG (+ optional fused cell) ----------
__global__ void __launch_bounds__(256) gemm_enc(const float* __restrict__ A,
                                                int do_cell,
                                                const float* __restrict__ xg,
                                                float* __restrict__ h_out) {
    __shared__ __align__(16) float As[16][64 + 4];
    __shared__ __align__(16) float Bs[16][64];
    __shared__ __align__(16) float Cs[64][64];

    const int tid = threadIdx.x;
    const int row0 = blockIdx.y * 64;
    const int n0 = blockIdx.x * 64;
    const int lr = tid >> 2, lk = (tid & 3) << 2;
    const int bk = tid >> 4, bn = (tid & 15) << 2;
    const int tm = tid & 15, tn = tid >> 4;

    float acc[4][4];
#pragma unroll
    for (int i = 0; i < 4; i++)
#pragma unroll
        for (int j = 0; j < 4; j++) acc[i][j] = 0.f;

    {
        float4 av = *reinterpret_cast<const float4*>(A + (size_t)(row0 + lr) * HSZ + lk);
        As[lk + 0][lr] = av.x; As[lk + 1][lr] = av.y;
        As[lk + 2][lr] = av.z; As[lk + 3][lr] = av.w;
        *reinterpret_cast<float4*>(&Bs[bk][bn]) =
            *reinterpret_cast<const float4*>(g_WencG + (size_t)bk * GSZ + n0 + bn);
    }
    __syncthreads();

    const int NKC = HSZ / 16;  // 32
    for (int kc = 0; kc < NKC; kc++) {
        float4 av; float4 bv;
        if (kc + 1 < NKC) {
            int k0 = (kc + 1) * 16;
            av = *reinterpret_cast<const float4*>(A + (size_t)(row0 + lr) * HSZ + k0 + lk);
            bv = *reinterpret_cast<const float4*>(g_WencG + (size_t)(k0 + bk) * GSZ + n0 + bn);
        }
#pragma unroll
        for (int k = 0; k < 16; k++) {
            float4 a4 = *reinterpret_cast<const float4*>(&As[k][tm * 4]);
            float4 b4 = *reinterpret_cast<const float4*>(&Bs[k][tn * 4]);
            float ar[4] = {a4.x, a4.y, a4.z, a4.w};
            float br[4] = {b4.x, b4.y, b4.z, b4.w};
#pragma unroll
            for (int i = 0; i < 4; i++)
#pragma unroll
                for (int j = 0; j < 4; j++) acc[i][j] = fmaf(ar[i], br[j], acc[i][j]);
        }
        __syncthreads();
        if (kc + 1 < NKC) {
            As[lk + 0][lr] = av.x; As[lk + 1][lr] = av.y;
            As[lk + 2][lr] = av.z; As[lk + 3][lr] = av.w;
            *reinterpret_cast<float4*>(&Bs[bk][bn]) = bv;
            __syncthreads();
        }
    }

    if (!do_cell) {
#pragma unroll
        for (int i = 0; i < 4; i++) {
            int b = row0 + tm * 4 + i;
#pragma unroll
            for (int j = 0; j < 4; j++)
                g_C[(size_t)b * GSZ + n0 + tn * 4 + j] = acc[i][j];
        }
        return;
    }

#pragma unroll
    for (int i = 0; i < 4; i++)
#pragma unroll
        for (int j = 0; j < 4; j++)
            Cs[tm * 4 + i][tn * 4 + j] = acc[i][j];
    __syncthreads();

    // cell: 16 quads x 64 rows
    for (int it = tid; it < 64 * 16; it += 256) {
        int r = it >> 4, qi = it & 15;
        int b = row0 + r;
        int hh = (n0 >> 2) + qi;
        const float* xr = xg + (size_t)b * ((size_t)SSZ * GSZ) + n0 + 4 * qi;
        int c4 = 4 * qi;
        float gi = __fadd_rn(xr[0], Cs[r][c4 + 0]);
        float gf = __fadd_rn(xr[1], Cs[r][c4 + 1]);
        float gg = __fadd_rn(xr[2], Cs[r][c4 + 2]);
        float go = __fadd_rn(xr[3], Cs[r][c4 + 3]);
        float si = sigf(gi), sf = sigf(gf), so = sigf(go);
        float tg = xtanh(gg);
        int idx = b * HSZ + hh;
        float cn = __fadd_rn(__fmul_rn(sf, g_c[idx]), __fmul_rn(si, tg));
        g_c[idx] = cn;
        h_out[idx] = __fmul_rn(so, xtanh(cn));
    }
}

// ---------- standalone encoder cell (t=0 only; interleaved) ----------
__global__ void __launch_bounds__(256) cell0_kernel(float* __restrict__ h_out,
                                                    const float* __restrict__ xg) {
    int idx = blockIdx.x * blockDim.x + threadIdx.x;
    int b = idx >> 9, hh = idx & (HSZ - 1);
    int n4 = 4 * hh;
    const float* Cb = g_C + (size_t)b * GSZ;
    const float* xr = xg + (size_t)b * ((size_t)SSZ * GSZ);
    float gi = __fadd_rn(xr[n4 + 0], Cb[n4 + 0]);
    float gf = __fadd_rn(xr[n4 + 1], Cb[n4 + 1]);
    float gg = __fadd_rn(xr[n4 + 2], Cb[n4 + 2]);
    float go = __fadd_rn(xr[n4 + 3], Cb[n4 + 3]);
    float si = sigf(gi), sf = sigf(gf), so = sigf(go);
    float tg = xtanh(gg);
    float cn = __fadd_rn(__fmul_rn(sf, g_c[idx]), __fmul_rn(si, tg));
    g_c[idx] = cn;
    h_out[idx] = __fmul_rn(so, xtanh(cn));
}

// ---------- big proj GEMM: [32768,512] = h_all[1..128] @ W1T + b1 ----------
__global__ void __launch_bounds__(256) proj_gemm(const float* __restrict__ b1) {
    __shared__ __align__(16) float As[16][64 + 4];
    __shared__ __align__(16) float Bs[16][64];
    const float* A = g_hall + (size_t)BSZ * HSZ;   // rows: r = s*BSZ + b
    const int tid = threadIdx.x;
    const int row0 = blockIdx.y * 64;
    const int n0 = blockIdx.x * 64;
    const int lr = tid >> 2, lk = (tid & 3) << 2;
    const int bk = tid >> 4, bn = (tid & 15) << 2;
    const int tm = tid & 15, tn = tid >> 4;

    float acc[4][4];
#pragma unroll
    for (int i = 0; i < 4; i++)
#pragma unroll
        for (int j = 0; j < 4; j++) acc[i][j] = 0.f;

    {
        float4 av = *reinterpret_cast<const float4*>(A + (size_t)(row0 + lr) * HSZ + lk);
        As[lk + 0][lr] = av.x; As[lk + 1][lr] = av.y;
        As[lk + 2][lr] = av.z; As[lk + 3][lr] = av.w;
        *reinterpret_cast<float4*>(&Bs[bk][bn]) =
            *reinterpret_cast<const float4*>(g_W1T + (size_t)bk * HSZ + n0 + bn);
    }
    __syncthreads();

    const int NKC = HSZ / 16;
    for (int kc = 0; kc < NKC; kc++) {
        float4 av; float4 bv;
        if (kc + 1 < NKC) {
            int k0 = (kc + 1) * 16;
            av = *reinterpret_cast<const float4*>(A + (size_t)(row0 + lr) * HSZ + k0 + lk);
            bv = *reinterpret_cast<const float4*>(g_W1T + (size_t)(k0 + bk) * HSZ + n0 + bn);
        }
#pragma unroll
        for (int k = 0; k < 16; k++) {
            float4 a4 = *reinterpret_cast<const float4*>(&As[k][tm * 4]);
            float4 b4 = *reinterpret_cast<const float4*>(&Bs[k][tn * 4]);
            float ar[4] = {a4.x, a4.y, a4.z, a4.w};
            float br[4] = {b4.x, b4.y, b4.z, b4.w};
#pragma unroll
            for (int i = 0; i < 4; i++)
#pragma unroll
                for (int j = 0; j < 4; j++) acc[i][j] = fmaf(ar[i], br[j], acc[i][j]);
        }
        __syncthreads();
        if (kc + 1 < NKC) {
            As[lk + 0][lr] = av.x; As[lk + 1][lr] = av.y;
            As[lk + 2][lr] = av.z; As[lk + 3][lr] = av.w;
            *reinterpret_cast<float4*>(&Bs[bk][bn]) = bv;
            __syncthreads();
        }
    }

#pragma unroll
    for (int i = 0; i < 4; i++) {
        int r = row0 + tm * 4 + i;
        int s = r >> 8, b = r & (BSZ - 1);
        size_t orow = ((size_t)b * SSZ + s) * HSZ;
#pragma unroll
        for (int j = 0; j < 4; j++) {
            int n = n0 + tn * 4 + j;
            g_proj[orow + n] = __fadd_rn(acc[i][j], b1[n]);
        }
    }
}

// ---------- decoder step GEMM [256,2560] (+ optional fused cell for t=0) ----------
#define BM 64
#define BN 80
__global__ void __launch_bounds__(256) gemm_dec(const float* __restrict__ A,
                                                float* __restrict__ dst2,
                                                const float* __restrict__ bias2,
                                                int do_cell,
                                                const float* __restrict__ xg0,
                                                float* __restrict__ h_out) {
    __shared__ __align__(16) float As[16][BM + 4];
    __shared__ __align__(16) float Bs[16][BN];
    __shared__ __align__(16) float Cs[BM][BN];

    const int tid = threadIdx.x;
    const int tm = tid & 15;
    const int tn = tid >> 4;
    const int row0 = blockIdx.y * BM;
    const int n0 = blockIdx.x * BN;
    const int lr = tid >> 2, lk = (tid & 3) << 2;
    const int bk = tid >> 4, bn = tid & 15;

    float acc[4][5];
#pragma unroll
    for (int i = 0; i < 4; i++)
#pragma unroll
        for (int j = 0; j < 5; j++) acc[i][j] = 0.f;

    {
        float4 av = *reinterpret_cast<const float4*>(A + (size_t)(row0 + lr) * HSZ + lk);
        As[lk + 0][lr] = av.x; As[lk + 1][lr] = av.y;
        As[lk + 2][lr] = av.z; As[lk + 3][lr] = av.w;
#pragma unroll
        for (int j = 0; j < 5; j++)
            Bs[bk][bn + 16 * j] = g_WdecT[(size_t)bk * NC + n0 + bn + 16 * j];
    }
    __syncthreads();

    const int NKC = HSZ / 16;
    for (int kc = 0; kc < NKC; kc++) {
        float4 av;
        float bv[5];
        if (kc + 1 < NKC) {
            int k0 = (kc + 1) * 16;
            av = *reinterpret_cast<const float4*>(A + (size_t)(row0 + lr) * HSZ + k0 + lk);
#pragma unroll
            for (int j = 0; j < 5; j++)
                bv[j] = g_WdecT[(size_t)(k0 + bk) * NC + n0 + bn + 16 * j];
        }
#pragma unroll
        for (int k = 0; k < 16; k++) {
            float4 a4 = *reinterpret_cast<const float4*>(&As[k][tm * 4]);
            float ar[4] = {a4.x, a4.y, a4.z, a4.w};
            float br[5];
#pragma unroll
            for (int j = 0; j < 5; j++) br[j] = Bs[k][tn + 16 * j];
#pragma unroll
            for (int i = 0; i < 4; i++)
#pragma unroll
                for (int j = 0; j < 5; j++) acc[i][j] = fmaf(ar[i], br[j], acc[i][j]);
        }
        __syncthreads();
        if (kc + 1 < NKC) {
            As[lk + 0][lr] = av.x; As[lk + 1][lr] = av.y;
            As[lk + 2][lr] = av.z; As[lk + 3][lr] = av.w;
#pragma unroll
            for (int j = 0; j < 5; j++) Bs[bk][bn + 16 * j] = bv[j];
            __syncthreads();
        }
    }

#pragma unroll
    for (int i = 0; i < 4; i++) {
        int b = row0 + tm * 4 + i;
#pragma unroll
        for (int j = 0; j < 5; j++) {
            int n = n0 + tn + 16 * j;
            if (n < GSZ) {
                if (do_cell) Cs[tm * 4 + i][tn + 16 * j] = acc[i][j];
                else         g_C[(size_t)b * GSZ + n] = acc[i][j];
            } else if (dst2) {
                dst2[(size_t)b * HSZ + (n - GSZ)] = __fadd_rn(acc[i][j], bias2[n - GSZ]);
            }
        }
    }

    if (do_cell) {
        __syncthreads();
        int gate_cols = (n0 < GSZ) ? min(GSZ - n0, BN) : 0;
        int nquads = gate_cols >> 2;
        int items = BM * nquads;
        for (int it = tid; it < items; it += 256) {
            int r = it / nquads, qi = it - r * nquads;
            int b = row0 + r;
            int hh = (n0 >> 2) + qi;
            const float* xr = xg0 + n0 + 4 * qi;   // xg0 broadcast across b
            int c4 = 4 * qi;
            float gi = __fadd_rn(xr[0], Cs[r][c4 + 0]);
            float gf = __fadd_rn(xr[1], Cs[r][c4 + 1]);
            float gg = __fadd_rn(xr[2], Cs[r][c4 + 2]);
            float go = __fadd_rn(xr[3], Cs[r][c4 + 3]);
            float si = sigf(gi), sf = sigf(gf), so = sigf(go);
            float tg = xtanh(gg);
            int idx = b * HSZ + hh;
            float cn = __fadd_rn(__fmul_rn(sf, g_c[idx]), __fmul_rn(si, tg));
            g_c[idx] = cn;
            h_out[idx] = __fmul_rn(so, xtanh(cn));
        }
    }
}

// ---------- attention phase 1: u dots, 2048 blocks ----------
__global__ void __launch_bounds__(256) attn_u_kernel(const float* __restrict__ V) {
    int b = blockIdx.x, qq = blockIdx.y;
    int tid = threadIdx.x, lane = tid & 31, w = tid >> 5;
    __shared__ float qs[HSZ];
    __shared__ float Vs[HSZ];
    for (int i = tid; i < HSZ; i += 256) {
        qs[i] = g_q[(size_t)b * HSZ + i];
        Vs[i] = V[i];
    }
    __syncthreads();
#pragma unroll
    for (int m = 0; m < 2; m++) {
        int s = qq * 16 + w + 8 * m;
        const float* pr = g_proj + ((size_t)b * SSZ + s) * HSZ;
        float acc = 0.f;
        for (int h = lane; h < HSZ; h += 32)
            acc = fmaf(xtanh(__fadd_rn(pr[h], qs[h])), Vs[h], acc);
#pragma unroll
        for (int o = 16; o; o >>= 1)
            acc = __fadd_rn(acc, __shfl_xor_sync(0xffffffffu, acc, o));
        if (lane == 0) g_us[b * SSZ + s] = g_mask[b * SSZ + s] ? acc : -10000.0f;
    }
}

// ---------- attention phase 2: softmax + argmax + mask + fused decoder cell ----------
__global__ void __launch_bounds__(128) attn_fin_kernel(int step,
                                                       float* __restrict__ out_probs,
                                                       float* __restrict__ out_idx,
                                                       float* __restrict__ h_out) {
    int b = blockIdx.x;
    int tid = threadIdx.x, lane = tid & 31, w = tid >> 5;
    __shared__ float us[SSZ];
    __shared__ float es[SSZ];
    __shared__ float ps[SSZ];
    __shared__ float s_mx, s_sum;
    __shared__ int s_idx;

    us[tid] = g_us[b * SSZ + tid];
    __syncthreads();

    if (w == 0) {
        float mv = fmaxf(us[lane], fmaxf(us[lane + 32], fmaxf(us[lane + 64], us[lane + 96])));
#pragma unroll
        for (int o = 16; o; o >>= 1) mv = fmaxf(mv, __shfl_xor_sync(0xffffffffu, mv, o));
        if (lane == 0) s_mx = mv;
    }
    __syncthreads();

    es[tid] = expf(__fadd_rn(us[tid], -s_mx));
    __syncthreads();

    if (w == 0) {
        float sv = __fadd_rn(__fadd_rn(es[lane], es[lane + 32]),
                             __fadd_rn(es[lane + 64], es[lane + 96]));
#pragma unroll
        for (int o = 16; o; o >>= 1)
            sv = __fadd_rn(sv, __shfl_xor_sync(0xffffffffu, sv, o));
        if (lane == 0) s_sum = sv;
    }
    __syncthreads();

    {
        float p = __fdiv_rn(es[tid], s_sum);
        ps[tid] = p;
        out_probs[((size_t)step * BSZ + b) * SSZ + tid] = p;
    }
    __syncthreads();

    if (w == 0) {
        float bv = -1.0f;
        int bi = 0;
#pragma unroll
        for (int k = 0; k < 4; k++) {
            int s = lane + 32 * k;
            float v = ps[s];
            if (v > bv) { bv = v; bi = s; }
        }
#pragma unroll
        for (int o = 16; o; o >>= 1) {
            float ov = __shfl_xor_sync(0xffffffffu, bv, o);
            int oi = __shfl_xor_sync(0xffffffffu, bi, o);
            if (ov > bv || (ov == bv && oi < bi)) { bv = ov; bi = oi; }
        }
        if (lane == 0) s_idx = bi;
    }
    __syncthreads();

    int bi = s_idx;
    if (tid == 0) {
        g_mask[b * SSZ + bi] = 0;
        if (out_idx) out_idx[(size_t)b * SSZ + step] = (float)bi;
    }

    if (h_out) {
        const float* Cb = g_C + (size_t)b * GSZ;
        const float* xr = g_xg_dec + ((size_t)b * SSZ + bi) * GSZ;
#pragma unroll
        for (int j = 0; j < 4; j++) {
            int hh = tid + 128 * j;
            int n4 = 4 * hh;
            int idx = b * HSZ + hh;
            float gi = __fadd_rn(xr[n4 + 0], Cb[n4 + 0]);
            float gf = __fadd_rn(xr[n4 + 1], Cb[n4 + 1]);
            float gg = __fadd_rn(xr[n4 + 2], Cb[n4 + 2]);
            float go = __fadd_rn(xr[n4 + 3], Cb[n4 + 3]);
            float si = sigf(gi), sf = sigf(gf), so = sigf(go);
            float tg = xtanh(gg);
            float cn = __fadd_rn(__fmul_rn(sf, g_c[idx]), __fmul_rn(si, tg));
            g_c[idx] = cn;
            h_out[idx] = __fmul_rn(so, xtanh(cn));
        }
    }
}

// ---------- host ----------
extern "C" void kernel_launch(void* const* d_in, const int* in_sizes, int n_in,
                              void* d_out, int out_size) {
    const float* inputs  = (const float*)d_in[0];
    const float* emb_W   = (const float*)d_in[2];
    const float* emb_b   = (const float*)d_in[3];
    const float* enc_Wih = (const float*)d_in[4];
    const float* enc_Whh = (const float*)d_in[5];
    const float* enc_bih = (const float*)d_in[6];
    const float* enc_bhh = (const float*)d_in[7];
    const float* h0      = (const float*)d_in[8];
    const float* c0      = (const float*)d_in[9];
    const float* dec0    = (const float*)d_in[10];
    const float* dec_Wih = (const float*)d_in[11];
    const float* dec_Whh = (const float*)d_in[12];
    const float* dec_bih = (const float*)d_in[13];
    const float* dec_bhh = (const float*)d_in[14];
    const float* W1      = (const float*)d_in[15];
    const float* b1      = (const float*)d_in[16];
    const float* W2      = (const float*)d_in[17];
    const float* b2      = (const float*)d_in[18];
    const float* V       = (const float*)d_in[19];

    float *phall, *phdec, *pq, *pxg_enc, *pxg0;
    cudaGetSymbolAddress((void**)&phall,   g_hall);
    cudaGetSymbolAddress((void**)&phdec,   g_hdec);
    cudaGetSymbolAddress((void**)&pq,      g_q);
    cudaGetSymbolAddress((void**)&pxg_enc, g_xg_enc);
    cudaGetSymbolAddress((void**)&pxg0,    g_xg0);

    float* out_probs = (float*)d_out;
    const size_t PROBS_N = (size_t)SSZ * BSZ * SSZ;
    float* out_idx = ((size_t)out_size >= PROBS_N + (size_t)BSZ * SSZ)
                         ? out_probs + PROBS_N : nullptr;

    dim3 ge(GSZ / 64, BSZ / 64);   // encoder gemm: 32 x 4 = 128 blocks
    dim3 gd(NC / BN, BSZ / BM);    // decoder gemm: 32 x 4 = 128 blocks
    dim3 gp(HSZ / 64, BSZ * SSZ / 64);  // proj gemm: 8 x 512
    dim3 gx(NB2 / 64, BSZ * SSZ / 64);
    dim3 ga(BSZ, 8);

    const size_t HB = (size_t)BSZ * HSZ;

    // prologue ordered so the profiled slot (index 3) is an encoder step GEMM
    init_kernel<<<(BSZ * HSZ + 255) / 256, 256>>>(h0, c0, inputs);                         // 0
    transpose_kernel<<<(HSZ * NC + 255) / 256, 256>>>(enc_Whh, W1, dec_Whh, W2);           // 1
    emb_kernel<<<(BSZ * SSZ * ESZ + 255) / 256, 256>>>(inputs, emb_W, emb_b);              // 2
    gemm_enc<<<ge, 256>>>(phall, 0, nullptr, nullptr);                                     // 3 (profiled)
    wiht_kernel<<<(ESZ * NB2 + 255) / 256, 256>>>(enc_Wih, dec_Wih);                       // 4
    xg_gemm<<<gx, 256>>>(enc_bih, enc_bhh, dec_bih, dec_bhh);                              // 5
    xg0_kernel<<<GSZ / 256, 256>>>(dec_Wih, dec_bih, dec_bhh, dec0);                       // 6
    cell0_kernel<<<BSZ * HSZ / 256, 256>>>(phall + HB, pxg_enc);                           // 7

    // encoder t = 1..127 (gemm + fused cell)
    for (int t = 1; t < SSZ; t++)
        gemm_enc<<<ge, 256>>>(phall + (size_t)t * HB, 1,
                              pxg_enc + (size_t)t * GSZ, phall + (size_t)(t + 1) * HB);

    // all proj at once
    proj_gemm<<<gp, 256>>>(b1);

    // decoder
    float* hb[2] = {phall + (size_t)SSZ * HB, phdec};
    int cur = 0;
    for (int t = 0; t < SSZ; t++) {
        if (t == 0) {
            gemm_dec<<<gd, 256>>>(hb[cur], nullptr, b2, 1, pxg0, hb[cur ^ 1]);
        } else {
            gemm_dec<<<gd, 256>>>(hb[cur], pq, b2, 0, nullptr, nullptr);
            attn_u_kernel<<<ga, 256>>>(V);
            attn_fin_kernel<<<BSZ, 128>>>(t - 1, out_probs, out_idx, hb[cur ^ 1]);
        }
        cur ^= 1;
    }
    gemm_dec<<<gd, 256>>>(hb[cur], pq, b2, 0, nullptr, nullptr);
    attn_u_kernel<<<ga, 256>>>(V);
    attn_fin_kernel<<<BSZ, 128>>>(SSZ - 1, out_probs, out_idx, nullptr);
}

// round 15
// speedup vs baseline: 1.7545x; 1.0170x over previous
#include <cuda_runtime.h>
#include <math.h>
#include <stddef.h>

#define BSZ 256
#define SSZ 128
#define ESZ 256
#define HSZ 512
#define GSZ 2048   // 4*H (interleaved gate cols)
#define NC  2560   // decoder: 2048 interleaved gates + 512 (q)
#define NB2 4096

// ---------- device scratch ----------
__device__ float  g_WencG[HSZ * GSZ];
__device__ float  g_W1T[HSZ * HSZ];
__device__ float  g_WdecT[HSZ * NC];
__device__ float  g_WihT[ESZ * NB2];
__device__ float  g_emb[(size_t)BSZ * SSZ * ESZ];
__device__ float  g_xg_enc[(size_t)BSZ * SSZ * GSZ];
__device__ float  g_xg_dec[(size_t)BSZ * SSZ * GSZ];
__device__ float  g_proj[(size_t)BSZ * SSZ * HSZ];
__device__ float  g_hall[(size_t)(SSZ + 1) * BSZ * HSZ];
__device__ float  g_hdec[BSZ * HSZ];
__device__ float  g_C[BSZ * GSZ];
__device__ float  g_c[BSZ * HSZ];
__device__ float  g_q[BSZ * HSZ];
__device__ float  g_xg0[GSZ];
__device__ float  g_us[BSZ * SSZ];
__device__ int    g_mask[BSZ * SSZ];

// ---------- frozen numerics ----------
__device__ __forceinline__ float xtanh(float x) { return tanhf(x); }
__device__ __forceinline__ float sigf(float x) {
    return __fdiv_rn(1.0f, __fadd_rn(1.0f, expf(-x)));
}
__device__ __forceinline__ int deint(int n) { return (n & 3) * HSZ + (n >> 2); }

// ---------- packed dual-lane FMA (each lane IEEE fp32 fma -> bitwise identical) ----------
__device__ __forceinline__ unsigned long long pack2(float lo, float hi) {
    unsigned long long r;
    asm("mov.b64 %0, {%1, %2};" : "=l"(r) : "f"(lo), "f"(hi));
    return r;
}
__device__ __forceinline__ void unpack2(unsigned long long v, float& lo, float& hi) {
    asm("mov.b64 {%0, %1}, %2;" : "=f"(lo), "=f"(hi) : "l"(v));
}
__device__ __forceinline__ void ffma2(unsigned long long& d, unsigned long long a, unsigned long long b) {
    asm("fma.rn.f32x2 %0, %1, %2, %3;" : "=l"(d) : "l"(a), "l"(b), "l"(d));
}

// ---------- state init ----------
__global__ void init_kernel(const float* __restrict__ h0, const float* __restrict__ c0,
                            const float* __restrict__ inputs) {
    int i = blockIdx.x * blockDim.x + threadIdx.x;
    if (i < BSZ * HSZ) {
        g_hall[i] = h0[i & (HSZ - 1)];
        g_c[i]    = c0[i & (HSZ - 1)];
    }
    if (i < BSZ * SSZ) g_mask[i] = (inputs[(size_t)i * 2] > 0.0f) ? 1 : 0;
}

// ---------- weight transposes ----------
__global__ void transpose_kernel(const float* __restrict__ encWhh, const float* __restrict__ W1,
                                 const float* __restrict__ decWhh, const float* __restrict__ W2) {
    int i = blockIdx.x * blockDim.x + threadIdx.x;
    if (i >= HSZ * NC) return;
    int k = i / NC, n = i % NC;
    if (n < GSZ) {
        int orig = deint(n);
        g_WencG[k * GSZ + n] = encWhh[orig * HSZ + k];
        g_WdecT[i] = decWhh[orig * HSZ + k];
    } else {
        int n2 = n - GSZ;
        g_W1T[k * HSZ + n2] = W1[n2 * HSZ + k];
        g_WdecT[i] = W2[n2 * HSZ + k];
    }
}
__global__ void wiht_kernel(const float* __restrict__ encWih, const float* __restrict__ decWih) {
    int i = blockIdx.x * blockDim.x + threadIdx.x;
    if (i >= ESZ * NB2) return;
    int k = i / NB2, n = i % NB2;
    float v;
    if (n < GSZ) v = encWih[deint(n) * ESZ + k];
    else         v = decWih[deint(n - GSZ) * ESZ + k];
    g_WihT[i] = v;
}

// ---------- emb ----------
__global__ void emb_kernel(const float* __restrict__ inputs, const float* __restrict__ embW,
                           const float* __restrict__ embB) {
    int i = blockIdx.x * blockDim.x + threadIdx.x;
    if (i >= BSZ * SSZ * ESZ) return;
    int e = i % ESZ, bs = i / ESZ;
    float in0 = inputs[(size_t)bs * 2], in1 = inputs[(size_t)bs * 2 + 1];
    float mm = fmaf(in1, embW[2 * e + 1], __fmul_rn(in0, embW[2 * e]));
    g_emb[i] = __fadd_rn(mm, embB[e]);
}

// ---------- decoder step-0 input gates ----------
__global__ void xg0_kernel(const float* __restrict__ decWih, const float* __restrict__ dbih,
                           const float* __restrict__ dbhh, const float* __restrict__ dec0) {
    int n = blockIdx.x * blockDim.x + threadIdx.x;
    if (n >= GSZ) return;
    int orig = deint(n);
    float acc = 0.f;
    for (int e = 0; e < ESZ; e++) acc = fmaf(dec0[e], decWih[orig * ESZ + e], acc);
    g_xg0[n] = __fadd_rn(__fadd_rn(acc, dbih[orig]), dbhh[orig]);
}

// ---------- xg precompute GEMM (f32x2 inner loop) ----------
__global__ void __launch_bounds__(256) xg_gemm(const float* __restrict__ ebih, const float* __restrict__ ebhh,
                                               const float* __restrict__ dbih, const float* __restrict__ dbhh) {
    __shared__ __align__(16) float As[16][64 + 4];
    __shared__ __align__(16) float Bs[16][64];
    const int tid = threadIdx.x;
    const int row0 = blockIdx.y * 64;
    const int n0 = blockIdx.x * 64;
    const int lr = tid >> 2, lk = (tid & 3) << 2;
    const int bk = tid >> 4, bn = (tid & 15) << 2;
    const int tm = tid & 15, tn = tid >> 4;

    unsigned long long acc2[4][2];
#pragma unroll
    for (int i = 0; i < 4; i++)
#pragma unroll
        for (int j = 0; j < 2; j++) acc2[i][j] = pack2(0.f, 0.f);

    {
        float4 av = *reinterpret_cast<const float4*>(g_emb + (size_t)(row0 + lr) * ESZ + lk);
        As[lk + 0][lr] = av.x; As[lk + 1][lr] = av.y;
        As[lk + 2][lr] = av.z; As[lk + 3][lr] = av.w;
        *reinterpret_cast<float4*>(&Bs[bk][bn]) =
            *reinterpret_cast<const float4*>(g_WihT + (size_t)bk * NB2 + n0 + bn);
    }
    __syncthreads();

    const int NKC = ESZ / 16;
    for (int kc = 0; kc < NKC; kc++) {
        float4 av; float4 bv;
        if (kc + 1 < NKC) {
            int k0 = (kc + 1) * 16;
            av = *reinterpret_cast<const float4*>(g_emb + (size_t)(row0 + lr) * ESZ + k0 + lk);
            bv = *reinterpret_cast<const float4*>(g_WihT + (size_t)(k0 + bk) * NB2 + n0 + bn);
        }
#pragma unroll
        for (int k = 0; k < 16; k++) {
            float4 a4 = *reinterpret_cast<const float4*>(&As[k][tm * 4]);
            float4 b4 = *reinterpret_cast<const float4*>(&Bs[k][tn * 4]);
            float ar[4] = {a4.x, a4.y, a4.z, a4.w};
            unsigned long long bp0 = pack2(b4.x, b4.y);
            unsigned long long bp1 = pack2(b4.z, b4.w);
#pragma unroll
            for (int i = 0; i < 4; i++) {
                unsigned long long ap = pack2(ar[i], ar[i]);
                ffma2(acc2[i][0], ap, bp0);
                ffma2(acc2[i][1], ap, bp1);
            }
        }
        __syncthreads();
        if (kc + 1 < NKC) {
            As[lk + 0][lr] = av.x; As[lk + 1][lr] = av.y;
            As[lk + 2][lr] = av.z; As[lk + 3][lr] = av.w;
            *reinterpret_cast<float4*>(&Bs[bk][bn]) = bv;
            __syncthreads();
        }
    }

#pragma unroll
    for (int i = 0; i < 4; i++) {
        size_t row = row0 + tm * 4 + i;
        float a0, a1, a2, a3;
        unpack2(acc2[i][0], a0, a1);
        unpack2(acc2[i][1], a2, a3);
        float accv[4] = {a0, a1, a2, a3};
#pragma unroll
        for (int j = 0; j < 4; j++) {
            int n = n0 + tn * 4 + j;
            if (n < GSZ) {
                int orig = deint(n);
                g_xg_enc[row * GSZ + n] = __fadd_rn(__fadd_rn(accv[j], ebih[orig]), ebhh[orig]);
            } else {
                int nd = n - GSZ;
                int orig = deint(nd);
                g_xg_dec[row * GSZ + nd] = __fadd_rn(__fadd_rn(accv[j], dbih[orig]), dbhh[orig]);
            }
        }
    }
}

// ---------- encoder step GEMM [256,2048] (+ fused cell), f32x2 inner loop ----------
__global__ void __launch_bounds__(256) gemm_enc(const float* __restrict__ A,
                                                int do_cell,
                                                const float* __restrict__ xg,
                                                float* __restrict__ h_out) {
    __shared__ __align__(16) float As[16][64 + 4];
    __shared__ __align__(16) float Bs[16][64];
    __shared__ __align__(16) float Cs[64][64];

    const int tid = threadIdx.x;
    const int row0 = blockIdx.y * 64;
    const int n0 = blockIdx.x * 64;
    const int lr = tid >> 2, lk = (tid & 3) << 2;
    const int bk = tid >> 4, bn = (tid & 15) << 2;
    const int tm = tid & 15, tn = tid >> 4;

    unsigned long long acc2[4][2];
#pragma unroll
    for (int i = 0; i < 4; i++)
#pragma unroll
        for (int j = 0; j < 2; j++) acc2[i][j] = pack2(0.f, 0.f);

    {
        float4 av = *reinterpret_cast<const float4*>(A + (size_t)(row0 + lr) * HSZ + lk);
        As[lk + 0][lr] = av.x; As[lk + 1][lr] = av.y;
        As[lk + 2][lr] = av.z; As[lk + 3][lr] = av.w;
        *reinterpret_cast<float4*>(&Bs[bk][bn]) =
            *reinterpret_cast<const float4*>(g_WencG + (size_t)bk * GSZ + n0 + bn);
    }
    __syncthreads();

    const int NKC = HSZ / 16;  // 32
    for (int kc = 0; kc < NKC; kc++) {
        float4 av; float4 bv;
        if (kc + 1 < NKC) {
            int k0 = (kc + 1) * 16;
            av = *reinterpret_cast<const float4*>(A + (size_t)(row0 + lr) * HSZ + k0 + lk);
            bv = *reinterpret_cast<const float4*>(g_WencG + (size_t)(k0 + bk) * GSZ + n0 + bn);
        }
#pragma unroll
        for (int k = 0; k < 16; k++) {
            float4 a4 = *reinterpret_cast<const float4*>(&As[k][tm * 4]);
            float4 b4 = *reinterpret_cast<const float4*>(&Bs[k][tn * 4]);
            float ar[4] = {a4.x, a4.y, a4.z, a4.w};
            unsigned long long bp0 = pack2(b4.x, b4.y);
            unsigned long long bp1 = pack2(b4.z, b4.w);
#pragma unroll
            for (int i = 0; i < 4; i++) {
                unsigned long long ap = pack2(ar[i], ar[i]);
                ffma2(acc2[i][0], ap, bp0);
                ffma2(acc2[i][1], ap, bp1);
            }
        }
        __syncthreads();
        if (kc + 1 < NKC) {
            As[lk + 0][lr] = av.x; As[lk + 1][lr] = av.y;
            As[lk + 2][lr] = av.z; As[lk + 3][lr] = av.w;
            *reinterpret_cast<float4*>(&Bs[bk][bn]) = bv;
            __syncthreads();
        }
    }

    if (!do_cell) {
#pragma unroll
        for (int i = 0; i < 4; i++) {
            int b = row0 + tm * 4 + i;
            float a0, a1, a2, a3;
            unpack2(acc2[i][0], a0, a1);
            unpack2(acc2[i][1], a2, a3);
            g_C[(size_t)b * GSZ + n0 + tn * 4 + 0] = a0;
            g_C[(size_t)b * GSZ + n0 + tn * 4 + 1] = a1;
            g_C[(size_t)b * GSZ + n0 + tn * 4 + 2] = a2;
            g_C[(size_t)b * GSZ + n0 + tn * 4 + 3] = a3;
        }
        return;
    }

#pragma unroll
    for (int i = 0; i < 4; i++) {
        float a0, a1, a2, a3;
        unpack2(acc2[i][0], a0, a1);
        unpack2(acc2[i][1], a2, a3);
        Cs[tm * 4 + i][tn * 4 + 0] = a0;
        Cs[tm * 4 + i][tn * 4 + 1] = a1;
        Cs[tm * 4 + i][tn * 4 + 2] = a2;
        Cs[tm * 4 + i][tn * 4 + 3] = a3;
    }
    __syncthreads();

    for (int it = tid; it < 64 * 16; it += 256) {
        int r = it >> 4, qi = it & 15;
        int b = row0 + r;
        int hh = (n0 >> 2) + qi;
        const float* xr = xg + (size_t)b * ((size_t)SSZ * GSZ) + n0 + 4 * qi;
        int c4 = 4 * qi;
        float gi = __fadd_rn(xr[0], Cs[r][c4 + 0]);
        float gf = __fadd_rn(xr[1], Cs[r][c4 + 1]);
        float gg = __fadd_rn(xr[2], Cs[r][c4 + 2]);
        float go = __fadd_rn(xr[3], Cs[r][c4 + 3]);
        float si = sigf(gi), sf = sigf(gf), so = sigf(go);
        float tg = xtanh(gg);
        int idx = b * HSZ + hh;
        float cn = __fadd_rn(__fmul_rn(sf, g_c[idx]), __fmul_rn(si, tg));
        g_c[idx] = cn;
        h_out[idx] = __fmul_rn(so, xtanh(cn));
    }
}

// ---------- standalone encoder cell (t=0) ----------
__global__ void __launch_bounds__(256) cell0_kernel(float* __restrict__ h_out,
                                                    const float* __restrict__ xg) {
    int idx = blockIdx.x * blockDim.x + threadIdx.x;
    int b = idx >> 9, hh = idx & (HSZ - 1);
    int n4 = 4 * hh;
    const float* Cb = g_C + (size_t)b * GSZ;
    const float* xr = xg + (size_t)b * ((size_t)SSZ * GSZ);
    float gi = __fadd_rn(xr[n4 + 0], Cb[n4 + 0]);
    float gf = __fadd_rn(xr[n4 + 1], Cb[n4 + 1]);
    float gg = __fadd_rn(xr[n4 + 2], Cb[n4 + 2]);
    float go = __fadd_rn(xr[n4 + 3], Cb[n4 + 3]);
    float si = sigf(gi), sf = sigf(gf), so = sigf(go);
    float tg = xtanh(gg);
    float cn = __fadd_rn(__fmul_rn(sf, g_c[idx]), __fmul_rn(si, tg));
    g_c[idx] = cn;
    h_out[idx] = __fmul_rn(so, xtanh(cn));
}

// ---------- big proj GEMM (f32x2 inner loop) ----------
__global__ void __launch_bounds__(256) proj_gemm(const float* __restrict__ b1) {
    __shared__ __align__(16) float As[16][64 + 4];
    __shared__ __align__(16) float Bs[16][64];
    const float* A = g_hall + (size_t)BSZ * HSZ;
    const int tid = threadIdx.x;
    const int row0 = blockIdx.y * 64;
    const int n0 = blockIdx.x * 64;
    const int lr = tid >> 2, lk = (tid & 3) << 2;
    const int bk = tid >> 4, bn = (tid & 15) << 2;
    const int tm = tid & 15, tn = tid >> 4;

    unsigned long long acc2[4][2];
#pragma unroll
    for (int i = 0; i < 4; i++)
#pragma unroll
        for (int j = 0; j < 2; j++) acc2[i][j] = pack2(0.f, 0.f);

    {
        float4 av = *reinterpret_cast<const float4*>(A + (size_t)(row0 + lr) * HSZ + lk);
        As[lk + 0][lr] = av.x; As[lk + 1][lr] = av.y;
        As[lk + 2][lr] = av.z; As[lk + 3][lr] = av.w;
        *reinterpret_cast<float4*>(&Bs[bk][bn]) =
            *reinterpret_cast<const float4*>(g_W1T + (size_t)bk * HSZ + n0 + bn);
    }
    __syncthreads();

    const int NKC = HSZ / 16;
    for (int kc = 0; kc < NKC; kc++) {
        float4 av; float4 bv;
        if (kc + 1 < NKC) {
            int k0 = (kc + 1) * 16;
            av = *reinterpret_cast<const float4*>(A + (size_t)(row0 + lr) * HSZ + k0 + lk);
            bv = *reinterpret_cast<const float4*>(g_W1T + (size_t)(k0 + bk) * HSZ + n0 + bn);
        }
#pragma unroll
        for (int k = 0; k < 16; k++) {
            float4 a4 = *reinterpret_cast<const float4*>(&As[k][tm * 4]);
            float4 b4 = *reinterpret_cast<const float4*>(&Bs[k][tn * 4]);
            float ar[4] = {a4.x, a4.y, a4.z, a4.w};
            unsigned long long bp0 = pack2(b4.x, b4.y);
            unsigned long long bp1 = pack2(b4.z, b4.w);
#pragma unroll
            for (int i = 0; i < 4; i++) {
                unsigned long long ap = pack2(ar[i], ar[i]);
                ffma2(acc2[i][0], ap, bp0);
                ffma2(acc2[i][1], ap, bp1);
            }
        }
        __syncthreads();
        if (kc + 1 < NKC) {
            As[lk + 0][lr] = av.x; As[lk + 1][lr] = av.y;
            As[lk + 2][lr] = av.z; As[lk + 3][lr] = av.w;
            *reinterpret_cast<float4*>(&Bs[bk][bn]) = bv;
            __syncthreads();
        }
    }

#pragma unroll
    for (int i = 0; i < 4; i++) {
        int r = row0 + tm * 4 + i;
        int s = r >> 8, b = r & (BSZ - 1);
        size_t orow = ((size_t)b * SSZ + s) * HSZ;
        float a0, a1, a2, a3;
        unpack2(acc2[i][0], a0, a1);
        unpack2(acc2[i][1], a2, a3);
        float accv[4] = {a0, a1, a2, a3};
#pragma unroll
        for (int j = 0; j < 4; j++) {
            int n = n0 + tn * 4 + j;
            g_proj[orow + n] = __fadd_rn(accv[j], b1[n]);
        }
    }
}

// ---------- decoder step GEMM [256,2560] (+ fused cell t=0), f32x2 inner loop ----------
#define BM 64
#define BN 80
__global__ void __launch_bounds__(256) gemm_dec(const float* __restrict__ A,
                                                float* __restrict__ dst2,
                                                const float* __restrict__ bias2,
                                                int do_cell,
                                                const float* __restrict__ xg0,
                                                float* __restrict__ h_out) {
    __shared__ __align__(16) float As[16][BM + 4];
    __shared__ __align__(16) float Bs[16][BN];
    __shared__ __align__(16) float Cs[BM][BN];

    const int tid = threadIdx.x;
    const int tm = tid & 15;
    const int tn = tid >> 4;
    const int row0 = blockIdx.y * BM;
    const int n0 = blockIdx.x * BN;
    const int lr = tid >> 2, lk = (tid & 3) << 2;
    const int bk = tid >> 4, bn = tid & 15;

    unsigned long long acc2[4][2];
    float acc4[4];
#pragma unroll
    for (int i = 0; i < 4; i++) {
        acc2[i][0] = pack2(0.f, 0.f);
        acc2[i][1] = pack2(0.f, 0.f);
        acc4[i] = 0.f;
    }

    {
        float4 av = *reinterpret_cast<const float4*>(A + (size_t)(row0 + lr) * HSZ + lk);
        As[lk + 0][lr] = av.x; As[lk + 1][lr] = av.y;
        As[lk + 2][lr] = av.z; As[lk + 3][lr] = av.w;
#pragma unroll
        for (int j = 0; j < 5; j++)
            Bs[bk][bn + 16 * j] = g_WdecT[(size_t)bk * NC + n0 + bn + 16 * j];
    }
    __syncthreads();

    const int NKC = HSZ / 16;
    for (int kc = 0; kc < NKC; kc++) {
        float4 av;
        float bv[5];
        if (kc + 1 < NKC) {
            int k0 = (kc + 1) * 16;
            av = *reinterpret_cast<const float4*>(A + (size_t)(row0 + lr) * HSZ + k0 + lk);
#pragma unroll
            for (int j = 0; j < 5; j++)
                bv[j] = g_WdecT[(size_t)(k0 + bk) * NC + n0 + bn + 16 * j];
        }
#pragma unroll
        for (int k = 0; k < 16; k++) {
            float4 a4 = *reinterpret_cast<const float4*>(&As[k][tm * 4]);
            float ar[4] = {a4.x, a4.y, a4.z, a4.w};
            float br[5];
#pragma unroll
            for (int j = 0; j < 5; j++) br[j] = Bs[k][tn + 16 * j];
            unsigned long long bp0 = pack2(br[0], br[1]);
            unsigned long long bp1 = pack2(br[2], br[3]);
#pragma unroll
            for (int i = 0; i < 4; i++) {
                unsigned long long ap = pack2(ar[i], ar[i]);
                ffma2(acc2[i][0], ap, bp0);
                ffma2(acc2[i][1], ap, bp1);
                acc4[i] = fmaf(ar[i], br[4], acc4[i]);
            }
        }
        __syncthreads();
        if (kc + 1 < NKC) {
            As[lk + 0][lr] = av.x; As[lk + 1][lr] = av.y;
            As[lk + 2][lr] = av.z; As[lk + 3][lr] = av.w;
#pragma unroll
            for (int j = 0; j < 5; j++) Bs[bk][bn + 16 * j] = bv[j];
            __syncthreads();
        }
    }

#pragma unroll
    for (int i = 0; i < 4; i++) {
        int b = row0 + tm * 4 + i;
        float a0, a1, a2, a3;
        unpack2(acc2[i][0], a0, a1);
        unpack2(acc2[i][1], a2, a3);
        float accv[5] = {a0, a1, a2, a3, acc4[i]};
#pragma unroll
        for (int j = 0; j < 5; j++) {
            int n = n0 + tn + 16 * j;
            if (n < GSZ) {
                if (do_cell) Cs[tm * 4 + i][tn + 16 * j] = accv[j];
                else         g_C[(size_t)b * GSZ + n] = accv[j];
            } else if (dst2) {
                dst2[(size_t)b * HSZ + (n - GSZ)] = __fadd_rn(accv[j], bias2[n - GSZ]);
            }
        }
    }

    if (do_cell) {
        __syncthreads();
        int gate_cols = (n0 < GSZ) ? min(GSZ - n0, BN) : 0;
        int nquads = gate_cols >> 2;
        int items = BM * nquads;
        for (int it = tid; it < items; it += 256) {
            int r = it / nquads, qi = it - r * nquads;
            int b = row0 + r;
            int hh = (n0 >> 2) + qi;
            const float* xr = xg0 + n0 + 4 * qi;
            int c4 = 4 * qi;
            float gi = __fadd_rn(xr[0], Cs[r][c4 + 0]);
            float gf = __fadd_rn(xr[1], Cs[r][c4 + 1]);
            float gg = __fadd_rn(xr[2], Cs[r][c4 + 2]);
            float go = __fadd_rn(xr[3], Cs[r][c4 + 3]);
            float si = sigf(gi), sf = sigf(gf), so = sigf(go);
            float tg = xtanh(gg);
            int idx = b * HSZ + hh;
            float cn = __fadd_rn(__fmul_rn(sf, g_c[idx]), __fmul_rn(si, tg));
            g_c[idx] = cn;
            h_out[idx] = __fmul_rn(so, xtanh(cn));
        }
    }
}

// ---------- attention phase 1: u dots, 2048 blocks ----------
__global__ void __launch_bounds__(256) attn_u_kernel(const float* __restrict__ V) {
    int b = blockIdx.x, qq = blockIdx.y;
    int tid = threadIdx.x, lane = tid & 31, w = tid >> 5;
    __shared__ float qs[HSZ];
    __shared__ float Vs[HSZ];
    for (int i = tid; i < HSZ; i += 256) {
        qs[i] = g_q[(size_t)b * HSZ + i];
        Vs[i] = V[i];
    }
    __syncthreads();
#pragma unroll
    for (int m = 0; m < 2; m++) {
        int s = qq * 16 + w + 8 * m;
        const float* pr = g_proj + ((size_t)b * SSZ + s) * HSZ;
        float acc = 0.f;
        for (int h = lane; h < HSZ; h += 32)
            acc = fmaf(xtanh(__fadd_rn(pr[h], qs[h])), Vs[h], acc);
#pragma unroll
        for (int o = 16; o; o >>= 1)
            acc = __fadd_rn(acc, __shfl_xor_sync(0xffffffffu, acc, o));
        if (lane == 0) g_us[b * SSZ + s] = g_mask[b * SSZ + s] ? acc : -10000.0f;
    }
}

// ---------- attention phase 2: softmax + argmax + mask + fused decoder cell ----------
__global__ void __launch_bounds__(128) attn_fin_kernel(int step,
                                                       float* __restrict__ out_probs,
                                                       float* __restrict__ out_idx,
                                                       float* __restrict__ h_out) {
    int b = blockIdx.x;
    int tid = threadIdx.x, lane = tid & 31, w = tid >> 5;
    __shared__ float us[SSZ];
    __shared__ float es[SSZ];
    __shared__ float ps[SSZ];
    __shared__ float s_mx, s_sum;
    __shared__ int s_idx;

    us[tid] = g_us[b * SSZ + tid];
    __syncthreads();

    if (w == 0) {
        float mv = fmaxf(us[lane], fmaxf(us[lane + 32], fmaxf(us[lane + 64], us[lane + 96])));
#pragma unroll
        for (int o = 16; o; o >>= 1) mv = fmaxf(mv, __shfl_xor_sync(0xffffffffu, mv, o));
        if (lane == 0) s_mx = mv;
    }
    __syncthreads();

    es[tid] = expf(__fadd_rn(us[tid], -s_mx));
    __syncthreads();

    if (w == 0) {
        float sv = __fadd_rn(__fadd_rn(es[lane], es[lane + 32]),
                             __fadd_rn(es[lane + 64], es[lane + 96]));
#pragma unroll
        for (int o = 16; o; o >>= 1)
            sv = __fadd_rn(sv, __shfl_xor_sync(0xffffffffu, sv, o));
        if (lane == 0) s_sum = sv;
    }
    __syncthreads();

    {
        float p = __fdiv_rn(es[tid], s_sum);
        ps[tid] = p;
        out_probs[((size_t)step * BSZ + b) * SSZ + tid] = p;
    }
    __syncthreads();

    if (w == 0) {
        float bv = -1.0f;
        int bi = 0;
#pragma unroll
        for (int k = 0; k < 4; k++) {
            int s = lane + 32 * k;
            float v = ps[s];
            if (v > bv) { bv = v; bi = s; }
        }
#pragma unroll
        for (int o = 16; o; o >>= 1) {
            float ov = __shfl_xor_sync(0xffffffffu, bv, o);
            int oi = __shfl_xor_sync(0xffffffffu, bi, o);
            if (ov > bv || (ov == bv && oi < bi)) { bv = ov; bi = oi; }
        }
        if (lane == 0) s_idx = bi;
    }
    __syncthreads();

    int bi = s_idx;
    if (tid == 0) {
        g_mask[b * SSZ + bi] = 0;
        if (out_idx) out_idx[(size_t)b * SSZ + step] = (float)bi;
    }

    if (h_out) {
        const float* Cb = g_C + (size_t)b * GSZ;
        const float* xr = g_xg_dec + ((size_t)b * SSZ + bi) * GSZ;
#pragma unroll
        for (int j = 0; j < 4; j++) {
            int hh = tid + 128 * j;
            int n4 = 4 * hh;
            int idx = b * HSZ + hh;
            float gi = __fadd_rn(xr[n4 + 0], Cb[n4 + 0]);
            float gf = __fadd_rn(xr[n4 + 1], Cb[n4 + 1]);
            float gg = __fadd_rn(xr[n4 + 2], Cb[n4 + 2]);
            float go = __fadd_rn(xr[n4 + 3], Cb[n4 + 3]);
            float si = sigf(gi), sf = sigf(gf), so = sigf(go);
            float tg = xtanh(gg);
            float cn = __fadd_rn(__fmul_rn(sf, g_c[idx]), __fmul_rn(si, tg));
            g_c[idx] = cn;
            h_out[idx] = __fmul_rn(so, xtanh(cn));
        }
    }
}

// ---------- host ----------
extern "C" void kernel_launch(void* const* d_in, const int* in_sizes, int n_in,
                              void* d_out, int out_size) {
    const float* inputs  = (const float*)d_in[0];
    const float* emb_W   = (const float*)d_in[2];
    const float* emb_b   = (const float*)d_in[3];
    const float* enc_Wih = (const float*)d_in[4];
    const float* enc_Whh = (const float*)d_in[5];
    const float* enc_bih = (const float*)d_in[6];
    const float* enc_bhh = (const float*)d_in[7];
    const float* h0      = (const float*)d_in[8];
    const float* c0      = (const float*)d_in[9];
    const float* dec0    = (const float*)d_in[10];
    const float* dec_Wih = (const float*)d_in[11];
    const float* dec_Whh = (const float*)d_in[12];
    const float* dec_bih = (const float*)d_in[13];
    const float* dec_bhh = (const float*)d_in[14];
    const float* W1      = (const float*)d_in[15];
    const float* b1      = (const float*)d_in[16];
    const float* W2      = (const float*)d_in[17];
    const float* b2      = (const float*)d_in[18];
    const float* V       = (const float*)d_in[19];

    float *phall, *phdec, *pq, *pxg_enc, *pxg0;
    cudaGetSymbolAddress((void**)&phall,   g_hall);
    cudaGetSymbolAddress((void**)&phdec,   g_hdec);
    cudaGetSymbolAddress((void**)&pq,      g_q);
    cudaGetSymbolAddress((void**)&pxg_enc, g_xg_enc);
    cudaGetSymbolAddress((void**)&pxg0,    g_xg0);

    float* out_probs = (float*)d_out;
    const size_t PROBS_N = (size_t)SSZ * BSZ * SSZ;
    float* out_idx = ((size_t)out_size >= PROBS_N + (size_t)BSZ * SSZ)
                         ? out_probs + PROBS_N : nullptr;

    dim3 ge(GSZ / 64, BSZ / 64);
    dim3 gd(NC / BN, BSZ / BM);
    dim3 gp(HSZ / 64, BSZ * SSZ / 64);
    dim3 gx(NB2 / 64, BSZ * SSZ / 64);
    dim3 ga(BSZ, 8);

    const size_t HB = (size_t)BSZ * HSZ;

    init_kernel<<<(BSZ * HSZ + 255) / 256, 256>>>(h0, c0, inputs);
    transpose_kernel<<<(HSZ * NC + 255) / 256, 256>>>(enc_Whh, W1, dec_Whh, W2);
    emb_kernel<<<(BSZ * SSZ * ESZ + 255) / 256, 256>>>(inputs, emb_W, emb_b);
    gemm_enc<<<ge, 256>>>(phall, 0, nullptr, nullptr);   // profiled slot
    wiht_kernel<<<(ESZ * NB2 + 255) / 256, 256>>>(enc_Wih, dec_Wih);
    xg_gemm<<<gx, 256>>>(enc_bih, enc_bhh, dec_bih, dec_bhh);
    xg0_kernel<<<GSZ / 256, 256>>>(dec_Wih, dec_bih, dec_bhh, dec0);
    cell0_kernel<<<BSZ * HSZ / 256, 256>>>(phall + HB, pxg_enc);

    for (int t = 1; t < SSZ; t++)
        gemm_enc<<<ge, 256>>>(phall + (size_t)t * HB, 1,
                              pxg_enc + (size_t)t * GSZ, phall + (size_t)(t + 1) * HB);

    proj_gemm<<<gp, 256>>>(b1);

    float* hb[2] = {phall + (size_t)SSZ * HB, phdec};
    int cur = 0;
    for (int t = 0; t < SSZ; t++) {
        if (t == 0) {
            gemm_dec<<<gd, 256>>>(hb[cur], nullptr, b2, 1, pxg0, hb[cur ^ 1]);
        } else {
            gemm_dec<<<gd, 256>>>(hb[cur], pq, b2, 0, nullptr, nullptr);
            attn_u_kernel<<<ga, 256>>>(V);
            attn_fin_kernel<<<BSZ, 128>>>(t - 1, out_probs, out_idx, hb[cur ^ 1]);
        }
        cur ^= 1;
    }
    gemm_dec<<<gd, 256>>>(hb[cur], pq, b2, 0, nullptr, nullptr);
    attn_u_kernel<<<ga, 256>>>(V);
    attn_fin_kernel<<<BSZ, 128>>>(SSZ - 1, out_probs, out_idx, nullptr);
}